// round 3
// baseline (speedup 1.0000x reference)
#include <cuda_runtime.h>
#include <math.h>

// ---------------- problem constants ----------------
#define D512 512
#define NH   8
#define DH   64
#define SSEQ 768
#define LSEQ 769          // S + 1 (CLS appended)
#define BMAX 32
#define NMAX 16384
#define MROWS (NMAX + BMAX)   // 16416

// ---------------- scratch (__device__ globals; no allocation allowed) ----------------
// All referenced by NAME inside device code only — no host-side symbol lookup.
__device__ __align__(256) float g_xd[BMAX * LSEQ * D512];
__device__ __align__(256) float g_q [BMAX * LSEQ * D512];
__device__ __align__(256) float g_k [BMAX * LSEQ * D512];
__device__ __align__(256) float g_v [BMAX * LSEQ * D512];
__device__ __align__(256) float g_at[BMAX * LSEQ * D512];
__device__ __align__(256) float g_ao[BMAX * LSEQ * D512];
__device__ __align__(256) float g_hn[MROWS * D512];
__device__ __align__(256) float g_t [MROWS * 1024];
__device__ __align__(256) float g_f [MROWS * D512];
__device__ int g_starts[BMAX + 1];

// compile-time scratch-buffer selector
#define BUF_XD 0
#define BUF_Q  1
#define BUF_K  2
#define BUF_V  3
#define BUF_AT 4
#define BUF_AO 5
#define BUF_HN 6
#define BUF_T  7
#define BUF_F  8
template<int ID> __device__ __forceinline__ float* gbuf() {
    if constexpr (ID == BUF_XD) return g_xd;
    else if constexpr (ID == BUF_Q)  return g_q;
    else if constexpr (ID == BUF_K)  return g_k;
    else if constexpr (ID == BUF_V)  return g_v;
    else if constexpr (ID == BUF_AT) return g_at;
    else if constexpr (ID == BUF_AO) return g_ao;
    else if constexpr (ID == BUF_HN) return g_hn;
    else if constexpr (ID == BUF_T)  return g_t;
    else return g_f;
}

// ---------------- starts[b] = lower_bound(batch, b); batch is sorted ----------------
__global__ void k_starts(const int* __restrict__ batch, int N, int B) {
    int b = threadIdx.x;
    if (b > B) return;
    int lo = 0, hi = N;
    while (lo < hi) {
        int mid = (lo + hi) >> 1;
        if (batch[mid] < b) lo = mid + 1; else hi = mid;
    }
    g_starts[b] = lo;
}

// ---------------- build dense xd[b, l, :] (zeros pad, CLS at l = S) ----------------
__global__ void k_build_xd(const float* __restrict__ x, const float* __restrict__ cls) {
    int row = blockIdx.x;            // b * LSEQ + l
    int b = row / LSEQ;
    int l = row - b * LSEQ;
    int tid = threadIdx.x;           // 128 threads -> 512 floats via float4
    int st  = g_starts[b];
    int cnt = g_starts[b + 1] - st;
    float4 v = make_float4(0.f, 0.f, 0.f, 0.f);
    if (l == SSEQ) {
        v = ((const float4*)(cls + (size_t)b * D512))[tid];
    } else if (l < cnt) {
        v = ((const float4*)(x + (size_t)(st + l) * D512))[tid];
    }
    ((float4*)(g_xd + (size_t)row * D512))[tid] = v;
}

// ---------------- generic SGEMM: C = A(MxK) @ W(KxN) + bias [+res] [relu] ----------------
// A, C, res are scratch buffers selected at compile time; W/bias are harness inputs.
// 128x128 tile, BK=8, 256 threads, 8x8 per thread. N multiple of 128, K multiple of 8.
template<bool RELU, int ABUF, int CBUF, int RBUF>
__global__ void __launch_bounds__(256) k_sgemm(
    const float* __restrict__ W, const float* __restrict__ bias,
    int M, int N, int K)
{
    const float* A = gbuf<ABUF>();
    float*       C = gbuf<CBUF>();

    __shared__ float As[8][128];
    __shared__ float Bs[8][128];
    int tid  = threadIdx.x;
    int brow = blockIdx.y * 128;
    int bcol = blockIdx.x * 128;

    int arow = tid >> 1;             // 0..127
    int acol = (tid & 1) << 2;       // 0 or 4
    int wrow = tid >> 5;             // 0..7
    int wcol = (tid & 31) << 2;      // 0..124
    int tr   = (tid >> 4) << 3;      // 0..120
    int tc   = (tid & 15) << 3;      // 0..120

    float acc[8][8];
#pragma unroll
    for (int i = 0; i < 8; i++)
#pragma unroll
        for (int j = 0; j < 8; j++) acc[i][j] = 0.f;

    int gr = brow + arow;
    bool aok = gr < M;
    const float* Ap = A + (size_t)(aok ? gr : (M - 1)) * K + acol;
    const float* Wp = W + (size_t)wrow * N + bcol + wcol;

    for (int k0 = 0; k0 < K; k0 += 8) {
        float4 av = aok ? *(const float4*)(Ap + k0) : make_float4(0.f, 0.f, 0.f, 0.f);
        As[acol + 0][arow] = av.x;
        As[acol + 1][arow] = av.y;
        As[acol + 2][arow] = av.z;
        As[acol + 3][arow] = av.w;
        *(float4*)&Bs[wrow][wcol] = *(const float4*)(Wp + (size_t)k0 * N);
        __syncthreads();
#pragma unroll
        for (int kk = 0; kk < 8; kk++) {
            float a[8], bb[8];
            *(float4*)(a)      = *(const float4*)&As[kk][tr];
            *(float4*)(a + 4)  = *(const float4*)&As[kk][tr + 4];
            *(float4*)(bb)     = *(const float4*)&Bs[kk][tc];
            *(float4*)(bb + 4) = *(const float4*)&Bs[kk][tc + 4];
#pragma unroll
            for (int i = 0; i < 8; i++)
#pragma unroll
                for (int j = 0; j < 8; j++)
                    acc[i][j] = fmaf(a[i], bb[j], acc[i][j]);
        }
        __syncthreads();
    }

#pragma unroll
    for (int i = 0; i < 8; i++) {
        int r = brow + tr + i;
        if (r < M) {
            float* cp = C + (size_t)r * N + bcol + tc;
#pragma unroll
            for (int j = 0; j < 8; j++) {
                float v = acc[i][j] + bias[bcol + tc + j];
                if constexpr (RBUF >= 0) {
                    const float* res = gbuf<(RBUF >= 0) ? RBUF : 0>();
                    v += res[(size_t)r * N + bcol + tc + j];
                }
                if (RELU) v = fmaxf(v, 0.f);
                cp[j] = v;
            }
        }
    }
}

// ---------------- fused flash attention (per (b, h, q-tile of 64)) ----------------
__global__ void __launch_bounds__(64) k_attn() {
    __shared__ float KV [64][64];    // K chunk, then reused for V chunk
    __shared__ float Ssh[64][65];    // per-query score row (padded: conflict-free)
    int b  = blockIdx.z;
    int h  = blockIdx.y;
    int qt = blockIdx.x;
    int tid = threadIdx.x;           // one query per thread
    int q = qt * 64 + tid;
    int cnt = g_starts[b + 1] - g_starts[b];
    bool qok = q < LSEQ;

    const float* qp = g_q + ((size_t)(b * LSEQ + (qok ? q : 0)) * D512) + h * DH;
    float qr[64];
#pragma unroll
    for (int i = 0; i < 16; i++) {
        float4 t = ((const float4*)qp)[i];
        qr[4*i] = t.x; qr[4*i+1] = t.y; qr[4*i+2] = t.z; qr[4*i+3] = t.w;
    }
    float o[64];
#pragma unroll
    for (int d = 0; d < 64; d++) o[d] = 0.f;
    float m = -1e30f, lsum = 0.f;

    for (int kt = 0; kt < 13; kt++) {     // 13 * 64 = 832 >= 769
        int kg = kt * 64 + tid;
        int kr = (kg < LSEQ) ? kg : (LSEQ - 1);
        const float* kp = g_k + ((size_t)(b * LSEQ + kr) * D512) + h * DH;
#pragma unroll
        for (int i = 0; i < 16; i++) ((float4*)KV[tid])[i] = ((const float4*)kp)[i];
        __syncthreads();

        float cmax = -1e30f;
        for (int k = 0; k < 64; k++) {
            float s = 0.f;
#pragma unroll
            for (int d = 0; d < 64; d++) s = fmaf(qr[d], KV[k][d], s);
            int kglob = kt * 64 + k;
            bool kvalid = (kglob < cnt) || (kglob == SSEQ);
            s = (kglob < LSEQ) ? (s * 0.125f + (kvalid ? 0.f : -1000000000.0f)) : -1e30f;
            Ssh[tid][k] = s;
            cmax = fmaxf(cmax, s);
        }
        __syncthreads();                   // done reading K chunk

        const float* vp = g_v + ((size_t)(b * LSEQ + kr) * D512) + h * DH;
#pragma unroll
        for (int i = 0; i < 16; i++) ((float4*)KV[tid])[i] = ((const float4*)vp)[i];
        __syncthreads();

        float mnew = fmaxf(m, cmax);
        float corr = __expf(m - mnew);
        m = mnew;
        lsum *= corr;
#pragma unroll
        for (int d = 0; d < 64; d++) o[d] *= corr;
        for (int k = 0; k < 64; k++) {
            float p = __expf(Ssh[tid][k] - m);
            lsum += p;
#pragma unroll
            for (int d = 0; d < 64; d++) o[d] = fmaf(p, KV[k][d], o[d]);
        }
        __syncthreads();                   // before next K load overwrites KV
    }

    if (qok) {
        float inv = 1.f / lsum;
        float* op = g_at + ((size_t)(b * LSEQ + q) * D512) + h * DH;
#pragma unroll
        for (int i = 0; i < 16; i++) {
            float4 t = make_float4(o[4*i] * inv, o[4*i+1] * inv, o[4*i+2] * inv, o[4*i+3] * inv);
            ((float4*)op)[i] = t;
        }
    }
}

// ---------------- LayerNorm row helper (128 threads = one 512-float row) ----------------
__device__ __forceinline__ void row_ln(const float* __restrict__ src,
                                       const float* __restrict__ gam,
                                       const float* __restrict__ bet,
                                       float* __restrict__ dst) {
    int tid = threadIdx.x;
    float4 v = ((const float4*)src)[tid];
    float s  = v.x + v.y + v.z + v.w;
    float ss = v.x*v.x + v.y*v.y + v.z*v.z + v.w*v.w;
#pragma unroll
    for (int off = 16; off; off >>= 1) {
        s  += __shfl_xor_sync(0xffffffffu, s,  off);
        ss += __shfl_xor_sync(0xffffffffu, ss, off);
    }
    __shared__ float sh[4][2];
    int w = tid >> 5;
    if ((tid & 31) == 0) { sh[w][0] = s; sh[w][1] = ss; }
    __syncthreads();
    s  = sh[0][0] + sh[1][0] + sh[2][0] + sh[3][0];
    ss = sh[0][1] + sh[1][1] + sh[2][1] + sh[3][1];
    float mean = s * (1.f / 512.f);
    float var  = ss * (1.f / 512.f) - mean * mean;
    float r = rsqrtf(var + 1e-5f);
    float4 gg = ((const float4*)gam)[tid];
    float4 bb = ((const float4*)bet)[tid];
    float4 out;
    out.x = (v.x - mean) * r * gg.x + bb.x;
    out.y = (v.y - mean) * r * gg.y + bb.y;
    out.z = (v.z - mean) * r * gg.z + bb.z;
    out.w = (v.w - mean) * r * gg.w + bb.w;
    ((float4*)dst)[tid] = out;
}

// gather valid rows (body + cls) from dense g_ao, then LN0 -> g_hn
__global__ void k_gather_ln(const int* __restrict__ batch,
                            const float* __restrict__ gam, const float* __restrict__ bet,
                            int N) {
    int row = blockIdx.x;            // 0 .. N+B-1
    const float* src;
    if (row < N) {
        int b = batch[row];
        int p = row - g_starts[b];
        src = g_ao + ((size_t)(b * LSEQ + p)) * D512;
    } else {
        int b = row - N;
        src = g_ao + ((size_t)(b * LSEQ + SSEQ)) * D512;
    }
    row_ln(src, gam, bet, g_hn + (size_t)row * D512);
}

// plain LN over g_f -> out (harness buffer)
__global__ void k_ln(const float* __restrict__ gam, const float* __restrict__ bet,
                     float* __restrict__ out) {
    int row = blockIdx.x;
    row_ln(g_f + (size_t)row * D512, gam, bet, out + (size_t)row * D512);
}

// ---------------- launch (no statics, no symbol lookups, launches only) ----------------
extern "C" void kernel_launch(void* const* d_in, const int* in_sizes, int n_in,
                              void* d_out, int out_size) {
    const float* x     = (const float*)d_in[0];
    const int*   batch = (const int*)  d_in[1];
    const float* cls   = (const float*)d_in[2];
    const float* Wq = (const float*)d_in[3];  const float* bq = (const float*)d_in[4];
    const float* Wk = (const float*)d_in[5];  const float* bk = (const float*)d_in[6];
    const float* Wv = (const float*)d_in[7];  const float* bv = (const float*)d_in[8];
    const float* Wo = (const float*)d_in[9];  const float* bo = (const float*)d_in[10];
    const float* W1 = (const float*)d_in[11]; const float* b1 = (const float*)d_in[12];
    const float* W2 = (const float*)d_in[13]; const float* b2 = (const float*)d_in[14];
    const float* g0 = (const float*)d_in[15]; const float* be0 = (const float*)d_in[16];
    const float* ga1 = (const float*)d_in[17]; const float* be1 = (const float*)d_in[18];

    int N = in_sizes[0] / D512;      // 16384
    int B = in_sizes[2] / D512;      // 32
    int M1 = B * LSEQ;               // 24608 dense rows
    int M2 = N + B;                  // 16416 output rows

    k_starts<<<1, 64>>>(batch, N, B);
    k_build_xd<<<M1, 128>>>(x, cls);

    dim3 gqkv((512 + 127) / 128, (M1 + 127) / 128);
    k_sgemm<false, BUF_XD, BUF_Q, -1><<<gqkv, 256>>>(Wq, bq, M1, 512, 512);
    k_sgemm<false, BUF_XD, BUF_K, -1><<<gqkv, 256>>>(Wk, bk, M1, 512, 512);
    k_sgemm<false, BUF_XD, BUF_V, -1><<<gqkv, 256>>>(Wv, bv, M1, 512, 512);

    k_attn<<<dim3(13, NH, B), 64>>>();

    k_sgemm<false, BUF_AT, BUF_AO, BUF_XD><<<gqkv, 256>>>(Wo, bo, M1, 512, 512);

    k_gather_ln<<<M2, 128>>>(batch, g0, be0, N);

    dim3 gf1((1024 + 127) / 128, (M2 + 127) / 128);
    k_sgemm<true,  BUF_HN, BUF_T, -1><<<gf1, 256>>>(W1, b1, M2, 1024, 512);
    dim3 gf2((512 + 127) / 128, (M2 + 127) / 128);
    k_sgemm<false, BUF_T, BUF_F, BUF_HN><<<gf2, 256>>>(W2, b2, M2, 512, 1024);

    k_ln<<<M2, 128>>>(ga1, be1, (float*)d_out);
}

// round 4
// speedup vs baseline: 1.4404x; 1.4404x over previous
#include <cuda_runtime.h>
#include <math.h>

// ---------------- problem constants ----------------
#define D512 512
#define NH   8
#define DH   64
#define SSEQ 768
#define LSEQ 769          // S + 1 (CLS appended)
#define BMAX 32
#define NMAX 16384
#define MROWS (NMAX + BMAX)   // 16416

// ---------------- scratch (__device__ globals; no allocation allowed) ----------------
__device__ __align__(256) float g_xd[BMAX * LSEQ * D512];
__device__ __align__(256) float g_q [BMAX * LSEQ * D512];
__device__ __align__(256) float g_k [BMAX * LSEQ * D512];
__device__ __align__(256) float g_v [BMAX * LSEQ * D512];
__device__ __align__(256) float g_at[BMAX * LSEQ * D512];
__device__ __align__(256) float g_ao[BMAX * LSEQ * D512];
__device__ __align__(256) float g_hn[MROWS * D512];
__device__ __align__(256) float g_t [MROWS * 1024];
__device__ __align__(256) float g_f [MROWS * D512];
__device__ int g_starts[BMAX + 1];

#define BUF_XD 0
#define BUF_Q  1
#define BUF_K  2
#define BUF_V  3
#define BUF_AT 4
#define BUF_AO 5
#define BUF_HN 6
#define BUF_T  7
#define BUF_F  8
template<int ID> __device__ __forceinline__ float* gbuf() {
    if constexpr (ID == BUF_XD) return g_xd;
    else if constexpr (ID == BUF_Q)  return g_q;
    else if constexpr (ID == BUF_K)  return g_k;
    else if constexpr (ID == BUF_V)  return g_v;
    else if constexpr (ID == BUF_AT) return g_at;
    else if constexpr (ID == BUF_AO) return g_ao;
    else if constexpr (ID == BUF_HN) return g_hn;
    else if constexpr (ID == BUF_T)  return g_t;
    else return g_f;
}

// ---------------- starts[b] ----------------
__global__ void k_starts(const int* __restrict__ batch, int N, int B) {
    int b = threadIdx.x;
    if (b > B) return;
    int lo = 0, hi = N;
    while (lo < hi) {
        int mid = (lo + hi) >> 1;
        if (batch[mid] < b) lo = mid + 1; else hi = mid;
    }
    g_starts[b] = lo;
}

// ---------------- build dense xd ----------------
__global__ void k_build_xd(const float* __restrict__ x, const float* __restrict__ cls) {
    int row = blockIdx.x;
    int b = row / LSEQ;
    int l = row - b * LSEQ;
    int tid = threadIdx.x;
    int st  = g_starts[b];
    int cnt = g_starts[b + 1] - st;
    float4 v = make_float4(0.f, 0.f, 0.f, 0.f);
    if (l == SSEQ) {
        v = ((const float4*)(cls + (size_t)b * D512))[tid];
    } else if (l < cnt) {
        v = ((const float4*)(x + (size_t)(st + l) * D512))[tid];
    }
    ((float4*)(g_xd + (size_t)row * D512))[tid] = v;
}

// ---------------- 3xTF32 tensor-core GEMM ----------------
// C = A(MxK) @ W(KxN) + bias [+res] [relu], fp32-class accuracy via hi/lo split.
// 128x128 tile, BK=16, 256 threads (8 warps of 64x32), mma.m16n8k8.tf32.

__device__ __forceinline__ unsigned tf32r(float x) {
    unsigned r;
    asm("cvt.rna.tf32.f32 %0, %1;" : "=r"(r) : "f"(x));
    return r;
}
__device__ __forceinline__ void split4(float4 v, uint4& h, uint4& l) {
    h.x = tf32r(v.x); l.x = tf32r(v.x - __uint_as_float(h.x));
    h.y = tf32r(v.y); l.y = tf32r(v.y - __uint_as_float(h.y));
    h.z = tf32r(v.z); l.z = tf32r(v.z - __uint_as_float(h.z));
    h.w = tf32r(v.w); l.w = tf32r(v.w - __uint_as_float(h.w));
}
__device__ __forceinline__ void mma8(float* c, const unsigned* a, const unsigned* b) {
    asm volatile(
        "mma.sync.aligned.m16n8k8.row.col.f32.tf32.tf32.f32 "
        "{%0,%1,%2,%3}, {%4,%5,%6,%7}, {%8,%9}, {%0,%1,%2,%3};"
        : "+f"(c[0]), "+f"(c[1]), "+f"(c[2]), "+f"(c[3])
        : "r"(a[0]), "r"(a[1]), "r"(a[2]), "r"(a[3]), "r"(b[0]), "r"(b[1]));
}

#define ASZ 2560            // 128 rows * 20 (16 k + pad4), m-major
#define BSZ 2176            // 16 k-rows * 136 (128 n + pad8), k-major
#define STG (2*ASZ + 2*BSZ) // 9472 floats per stage
#define GEMM_SMEM (2 * STG * 4)  // 75776 bytes

template<bool RELU, int ABUF, int CBUF, int RBUF>
__global__ void __launch_bounds__(256) k_mma(
    const float* __restrict__ W, const float* __restrict__ bias,
    int M, int N, int K)
{
    const float* A = gbuf<ABUF>();
    float*       C = gbuf<CBUF>();

    extern __shared__ unsigned smu[];
    int tid  = threadIdx.x;
    int lane = tid & 31;
    int warp = tid >> 5;
    int wm = warp >> 2;          // 0..1
    int wn = warp & 3;           // 0..3
    int brow = blockIdx.y * 128;
    int bcol = blockIdx.x * 128;

    float acc[4][4][4];
#pragma unroll
    for (int mt = 0; mt < 4; mt++)
#pragma unroll
        for (int nt = 0; nt < 4; nt++)
#pragma unroll
            for (int i = 0; i < 4; i++) acc[mt][nt][i] = 0.f;

    // per-thread global staging coords
    int ar0 = tid >> 2, aq0 = tid & 3;              // A: element tid
    int ar1 = (tid + 256) >> 2, aq1 = aq0;          // A: element tid+256
    int bk0 = tid >> 5, bq0 = tid & 31;             // B(W): element tid
    int bk1 = (tid + 256) >> 5, bq1 = bq0;          // element tid+256

    int nchunks = K >> 4;
    float4 av0, av1, bv0, bv1;

    // prologue: load chunk 0
    {
        int gr0 = brow + ar0, gr1 = brow + ar1;
        av0 = (gr0 < M) ? *(const float4*)(A + (size_t)gr0 * K + aq0 * 4) : make_float4(0,0,0,0);
        av1 = (gr1 < M) ? *(const float4*)(A + (size_t)gr1 * K + aq1 * 4) : make_float4(0,0,0,0);
        bv0 = *(const float4*)(W + (size_t)bk0 * N + bcol + bq0 * 4);
        bv1 = *(const float4*)(W + (size_t)bk1 * N + bcol + bq1 * 4);
        unsigned* AsHi = smu; unsigned* AsLo = smu + ASZ;
        unsigned* BsHi = smu + 2*ASZ; unsigned* BsLo = smu + 2*ASZ + BSZ;
        uint4 h, l;
        split4(av0, h, l); *(uint4*)(AsHi + ar0*20 + aq0*4) = h; *(uint4*)(AsLo + ar0*20 + aq0*4) = l;
        split4(av1, h, l); *(uint4*)(AsHi + ar1*20 + aq1*4) = h; *(uint4*)(AsLo + ar1*20 + aq1*4) = l;
        split4(bv0, h, l); *(uint4*)(BsHi + bk0*136 + bq0*4) = h; *(uint4*)(BsLo + bk0*136 + bq0*4) = l;
        split4(bv1, h, l); *(uint4*)(BsHi + bk1*136 + bq1*4) = h; *(uint4*)(BsLo + bk1*136 + bq1*4) = l;
    }

    int r = lane >> 2, cl = lane & 3;
    for (int ch = 0; ch < nchunks; ch++) {
        __syncthreads();
        // prefetch next chunk into registers
        if (ch + 1 < nchunks) {
            int k0 = (ch + 1) << 4;
            int gr0 = brow + ar0, gr1 = brow + ar1;
            av0 = (gr0 < M) ? *(const float4*)(A + (size_t)gr0 * K + k0 + aq0 * 4) : make_float4(0,0,0,0);
            av1 = (gr1 < M) ? *(const float4*)(A + (size_t)gr1 * K + k0 + aq1 * 4) : make_float4(0,0,0,0);
            bv0 = *(const float4*)(W + (size_t)(k0 + bk0) * N + bcol + bq0 * 4);
            bv1 = *(const float4*)(W + (size_t)(k0 + bk1) * N + bcol + bq1 * 4);
        }
        // compute over current stage
        unsigned* base = smu + (ch & 1) * STG;
        unsigned* AsHi = base; unsigned* AsLo = base + ASZ;
        unsigned* BsHi = base + 2*ASZ; unsigned* BsLo = base + 2*ASZ + BSZ;
#pragma unroll
        for (int kk = 0; kk < 16; kk += 8) {
            unsigned ah[4][4], al[4][4], bh[4][2], bl[4][2];
#pragma unroll
            for (int mt = 0; mt < 4; mt++) {
                int o = (wm*64 + mt*16 + r) * 20 + kk + cl;
                ah[mt][0] = AsHi[o];       ah[mt][1] = AsHi[o + 160];
                ah[mt][2] = AsHi[o + 4];   ah[mt][3] = AsHi[o + 164];
                al[mt][0] = AsLo[o];       al[mt][1] = AsLo[o + 160];
                al[mt][2] = AsLo[o + 4];   al[mt][3] = AsLo[o + 164];
            }
#pragma unroll
            for (int nt = 0; nt < 4; nt++) {
                int o = (kk + cl) * 136 + wn*32 + nt*8 + r;
                bh[nt][0] = BsHi[o];  bh[nt][1] = BsHi[o + 544];
                bl[nt][0] = BsLo[o];  bl[nt][1] = BsLo[o + 544];
            }
#pragma unroll
            for (int mt = 0; mt < 4; mt++)
#pragma unroll
                for (int nt = 0; nt < 4; nt++) {
                    mma8(acc[mt][nt], ah[mt], bh[nt]);   // hi*hi
                    mma8(acc[mt][nt], al[mt], bh[nt]);   // lo*hi
                    mma8(acc[mt][nt], ah[mt], bl[nt]);   // hi*lo
                }
        }
        __syncthreads();
        // store prefetched chunk into the other stage
        if (ch + 1 < nchunks) {
            unsigned* nb = smu + ((ch + 1) & 1) * STG;
            unsigned* nAsHi = nb; unsigned* nAsLo = nb + ASZ;
            unsigned* nBsHi = nb + 2*ASZ; unsigned* nBsLo = nb + 2*ASZ + BSZ;
            uint4 h, l;
            split4(av0, h, l); *(uint4*)(nAsHi + ar0*20 + aq0*4) = h; *(uint4*)(nAsLo + ar0*20 + aq0*4) = l;
            split4(av1, h, l); *(uint4*)(nAsHi + ar1*20 + aq1*4) = h; *(uint4*)(nAsLo + ar1*20 + aq1*4) = l;
            split4(bv0, h, l); *(uint4*)(nBsHi + bk0*136 + bq0*4) = h; *(uint4*)(nBsLo + bk0*136 + bq0*4) = l;
            split4(bv1, h, l); *(uint4*)(nBsHi + bk1*136 + bq1*4) = h; *(uint4*)(nBsLo + bk1*136 + bq1*4) = l;
        }
    }

    // epilogue
#pragma unroll
    for (int mt = 0; mt < 4; mt++) {
        int row0 = brow + wm*64 + mt*16 + r;
        int row1 = row0 + 8;
#pragma unroll
        for (int nt = 0; nt < 4; nt++) {
            int col = bcol + wn*32 + nt*8 + cl*2;
            float2 bb = *(const float2*)(bias + col);
            const float* c = acc[mt][nt];
            if (row0 < M) {
                float v0 = c[0] + bb.x, v1 = c[1] + bb.y;
                if constexpr (RBUF >= 0) {
                    const float* res = gbuf<(RBUF >= 0) ? RBUF : 0>();
                    float2 rv = *(const float2*)(res + (size_t)row0 * N + col);
                    v0 += rv.x; v1 += rv.y;
                }
                if (RELU) { v0 = fmaxf(v0, 0.f); v1 = fmaxf(v1, 0.f); }
                *(float2*)(C + (size_t)row0 * N + col) = make_float2(v0, v1);
            }
            if (row1 < M) {
                float v0 = c[2] + bb.x, v1 = c[3] + bb.y;
                if constexpr (RBUF >= 0) {
                    const float* res = gbuf<(RBUF >= 0) ? RBUF : 0>();
                    float2 rv = *(const float2*)(res + (size_t)row1 * N + col);
                    v0 += rv.x; v1 += rv.y;
                }
                if (RELU) { v0 = fmaxf(v0, 0.f); v1 = fmaxf(v1, 0.f); }
                *(float2*)(C + (size_t)row1 * N + col) = make_float2(v0, v1);
            }
        }
    }
}

// ---------------- fused flash attention (per (b, h, q-tile of 64)) ----------------
__global__ void __launch_bounds__(64) k_attn() {
    __shared__ float KV [64][64];
    __shared__ float Ssh[64][65];
    int b  = blockIdx.z;
    int h  = blockIdx.y;
    int qt = blockIdx.x;
    int tid = threadIdx.x;
    int q = qt * 64 + tid;
    int cnt = g_starts[b + 1] - g_starts[b];
    // skip q-tiles that contain no valid queries (their outputs are never gathered)
    if (!((qt * 64 < cnt) || (qt == 12))) return;
    bool qok = q < LSEQ;

    const float* qp = g_q + ((size_t)(b * LSEQ + (qok ? q : 0)) * D512) + h * DH;
    float qr[64];
#pragma unroll
    for (int i = 0; i < 16; i++) {
        float4 t = ((const float4*)qp)[i];
        qr[4*i] = t.x; qr[4*i+1] = t.y; qr[4*i+2] = t.z; qr[4*i+3] = t.w;
    }
    float o[64];
#pragma unroll
    for (int d = 0; d < 64; d++) o[d] = 0.f;
    float m = -1e30f, lsum = 0.f;

    for (int kt = 0; kt < 13; kt++) {
        // skip k-chunks with no valid keys: their probabilities are exactly 0
        if (!((kt * 64 < cnt) || (kt == 12))) continue;
        int kg = kt * 64 + tid;
        int kr = (kg < LSEQ) ? kg : (LSEQ - 1);
        const float* kp = g_k + ((size_t)(b * LSEQ + kr) * D512) + h * DH;
#pragma unroll
        for (int i = 0; i < 16; i++) ((float4*)KV[tid])[i] = ((const float4*)kp)[i];
        __syncthreads();

        float cmax = -1e30f;
        for (int k = 0; k < 64; k++) {
            float s = 0.f;
#pragma unroll
            for (int d = 0; d < 64; d++) s = fmaf(qr[d], KV[k][d], s);
            int kglob = kt * 64 + k;
            bool kvalid = (kglob < cnt) || (kglob == SSEQ);
            s = (kglob < LSEQ) ? (s * 0.125f + (kvalid ? 0.f : -1000000000.0f)) : -1e30f;
            Ssh[tid][k] = s;
            cmax = fmaxf(cmax, s);
        }
        __syncthreads();

        const float* vp = g_v + ((size_t)(b * LSEQ + kr) * D512) + h * DH;
#pragma unroll
        for (int i = 0; i < 16; i++) ((float4*)KV[tid])[i] = ((const float4*)vp)[i];
        __syncthreads();

        float mnew = fmaxf(m, cmax);
        float corr = __expf(m - mnew);
        m = mnew;
        lsum *= corr;
#pragma unroll
        for (int d = 0; d < 64; d++) o[d] *= corr;
        for (int k = 0; k < 64; k++) {
            float p = __expf(Ssh[tid][k] - m);
            lsum += p;
#pragma unroll
            for (int d = 0; d < 64; d++) o[d] = fmaf(p, KV[k][d], o[d]);
        }
        __syncthreads();
    }

    if (qok) {
        float inv = 1.f / lsum;
        float* op = g_at + ((size_t)(b * LSEQ + q) * D512) + h * DH;
#pragma unroll
        for (int i = 0; i < 16; i++) {
            float4 t = make_float4(o[4*i] * inv, o[4*i+1] * inv, o[4*i+2] * inv, o[4*i+3] * inv);
            ((float4*)op)[i] = t;
        }
    }
}

// ---------------- LayerNorm ----------------
__device__ __forceinline__ void row_ln(const float* __restrict__ src,
                                       const float* __restrict__ gam,
                                       const float* __restrict__ bet,
                                       float* __restrict__ dst) {
    int tid = threadIdx.x;
    float4 v = ((const float4*)src)[tid];
    float s  = v.x + v.y + v.z + v.w;
    float ss = v.x*v.x + v.y*v.y + v.z*v.z + v.w*v.w;
#pragma unroll
    for (int off = 16; off; off >>= 1) {
        s  += __shfl_xor_sync(0xffffffffu, s,  off);
        ss += __shfl_xor_sync(0xffffffffu, ss, off);
    }
    __shared__ float sh[4][2];
    int w = tid >> 5;
    if ((tid & 31) == 0) { sh[w][0] = s; sh[w][1] = ss; }
    __syncthreads();
    s  = sh[0][0] + sh[1][0] + sh[2][0] + sh[3][0];
    ss = sh[0][1] + sh[1][1] + sh[2][1] + sh[3][1];
    float mean = s * (1.f / 512.f);
    float var  = ss * (1.f / 512.f) - mean * mean;
    float rr = rsqrtf(var + 1e-5f);
    float4 gg = ((const float4*)gam)[tid];
    float4 bb = ((const float4*)bet)[tid];
    float4 out;
    out.x = (v.x - mean) * rr * gg.x + bb.x;
    out.y = (v.y - mean) * rr * gg.y + bb.y;
    out.z = (v.z - mean) * rr * gg.z + bb.z;
    out.w = (v.w - mean) * rr * gg.w + bb.w;
    ((float4*)dst)[tid] = out;
}

__global__ void k_gather_ln(const int* __restrict__ batch,
                            const float* __restrict__ gam, const float* __restrict__ bet,
                            int N) {
    int row = blockIdx.x;
    const float* src;
    if (row < N) {
        int b = batch[row];
        int p = row - g_starts[b];
        src = g_ao + ((size_t)(b * LSEQ + p)) * D512;
    } else {
        int b = row - N;
        src = g_ao + ((size_t)(b * LSEQ + SSEQ)) * D512;
    }
    row_ln(src, gam, bet, g_hn + (size_t)row * D512);
}

__global__ void k_ln(const float* __restrict__ gam, const float* __restrict__ bet,
                     float* __restrict__ out) {
    int row = blockIdx.x;
    row_ln(g_f + (size_t)row * D512, gam, bet, out + (size_t)row * D512);
}

// ---------------- launch ----------------
extern "C" void kernel_launch(void* const* d_in, const int* in_sizes, int n_in,
                              void* d_out, int out_size) {
    const float* x     = (const float*)d_in[0];
    const int*   batch = (const int*)  d_in[1];
    const float* cls   = (const float*)d_in[2];
    const float* Wq = (const float*)d_in[3];  const float* bq = (const float*)d_in[4];
    const float* Wk = (const float*)d_in[5];  const float* bk = (const float*)d_in[6];
    const float* Wv = (const float*)d_in[7];  const float* bv = (const float*)d_in[8];
    const float* Wo = (const float*)d_in[9];  const float* bo = (const float*)d_in[10];
    const float* W1 = (const float*)d_in[11]; const float* b1 = (const float*)d_in[12];
    const float* W2 = (const float*)d_in[13]; const float* b2 = (const float*)d_in[14];
    const float* g0 = (const float*)d_in[15]; const float* be0 = (const float*)d_in[16];
    const float* ga1 = (const float*)d_in[17]; const float* be1 = (const float*)d_in[18];

    int N = in_sizes[0] / D512;      // 16384
    int B = in_sizes[2] / D512;      // 32
    int M1 = B * LSEQ;               // 24608
    int M2 = N + B;                  // 16416

    // opt-in dynamic smem (idempotent host calls; capture-safe: no stream ops)
    cudaFuncSetAttribute(k_mma<false, BUF_XD, BUF_Q, -1>,     cudaFuncAttributeMaxDynamicSharedMemorySize, GEMM_SMEM);
    cudaFuncSetAttribute(k_mma<false, BUF_XD, BUF_K, -1>,     cudaFuncAttributeMaxDynamicSharedMemorySize, GEMM_SMEM);
    cudaFuncSetAttribute(k_mma<false, BUF_XD, BUF_V, -1>,     cudaFuncAttributeMaxDynamicSharedMemorySize, GEMM_SMEM);
    cudaFuncSetAttribute(k_mma<false, BUF_AT, BUF_AO, BUF_XD>,cudaFuncAttributeMaxDynamicSharedMemorySize, GEMM_SMEM);
    cudaFuncSetAttribute(k_mma<true,  BUF_HN, BUF_T, -1>,     cudaFuncAttributeMaxDynamicSharedMemorySize, GEMM_SMEM);
    cudaFuncSetAttribute(k_mma<false, BUF_T, BUF_F, BUF_HN>,  cudaFuncAttributeMaxDynamicSharedMemorySize, GEMM_SMEM);

    k_starts<<<1, 64>>>(batch, N, B);
    k_build_xd<<<M1, 128>>>(x, cls);

    dim3 gqkv(512 / 128, (M1 + 127) / 128);
    k_mma<false, BUF_XD, BUF_Q, -1><<<gqkv, 256, GEMM_SMEM>>>(Wq, bq, M1, 512, 512);
    k_mma<false, BUF_XD, BUF_K, -1><<<gqkv, 256, GEMM_SMEM>>>(Wk, bk, M1, 512, 512);
    k_mma<false, BUF_XD, BUF_V, -1><<<gqkv, 256, GEMM_SMEM>>>(Wv, bv, M1, 512, 512);

    k_attn<<<dim3(13, NH, B), 64>>>();

    k_mma<false, BUF_AT, BUF_AO, BUF_XD><<<gqkv, 256, GEMM_SMEM>>>(Wo, bo, M1, 512, 512);

    k_gather_ln<<<M2, 128>>>(batch, g0, be0, N);

    dim3 gf1(1024 / 128, (M2 + 127) / 128);
    k_mma<true,  BUF_HN, BUF_T, -1><<<gf1, 256, GEMM_SMEM>>>(W1, b1, M2, 1024, 512);
    dim3 gf2(512 / 128, (M2 + 127) / 128);
    k_mma<false, BUF_T, BUF_F, BUF_HN><<<gf2, 256, GEMM_SMEM>>>(W2, b2, M2, 512, 1024);

    k_ln<<<M2, 128>>>(ga1, be1, (float*)d_out);
}

// round 5
// speedup vs baseline: 1.9320x; 1.3413x over previous
#include <cuda_runtime.h>
#include <cuda_bf16.h>
#include <math.h>

// ---------------- problem constants ----------------
#define D512 512
#define NH   8
#define DH   64
#define SSEQ 768
#define LSEQ 769          // S + 1 (CLS appended)
#define BMAX 32
#define NMAX 16384
#define MROWS (NMAX + BMAX)   // 16416

// ---------------- scratch (__device__ globals; no allocation allowed) ----------------
__device__ __align__(256) float g_xd[BMAX * LSEQ * D512];
__device__ __align__(256) float g_q [BMAX * LSEQ * D512];
__device__ __align__(256) float g_k [BMAX * LSEQ * D512];
__device__ __align__(256) float g_v [BMAX * LSEQ * D512];
__device__ __align__(256) float g_at[BMAX * LSEQ * D512];
__device__ __align__(256) float g_ao[BMAX * LSEQ * D512];
__device__ __align__(256) float g_hn[MROWS * D512];
__device__ __align__(256) float g_t [MROWS * 1024];
__device__ __align__(256) float g_f [MROWS * D512];
__device__ int g_starts[BMAX + 1];

#define BUF_XD 0
#define BUF_Q  1
#define BUF_K  2
#define BUF_V  3
#define BUF_AT 4
#define BUF_AO 5
#define BUF_HN 6
#define BUF_T  7
#define BUF_F  8
template<int ID> __device__ __forceinline__ float* gbuf() {
    if constexpr (ID == BUF_XD) return g_xd;
    else if constexpr (ID == BUF_Q)  return g_q;
    else if constexpr (ID == BUF_K)  return g_k;
    else if constexpr (ID == BUF_V)  return g_v;
    else if constexpr (ID == BUF_AT) return g_at;
    else if constexpr (ID == BUF_AO) return g_ao;
    else if constexpr (ID == BUF_HN) return g_hn;
    else if constexpr (ID == BUF_T)  return g_t;
    else return g_f;
}

// ---------------- starts[b] ----------------
__global__ void k_starts(const int* __restrict__ batch, int N, int B) {
    int b = threadIdx.x;
    if (b > B) return;
    int lo = 0, hi = N;
    while (lo < hi) {
        int mid = (lo + hi) >> 1;
        if (batch[mid] < b) lo = mid + 1; else hi = mid;
    }
    g_starts[b] = lo;
}

// ---------------- build dense xd ----------------
__global__ void k_build_xd(const float* __restrict__ x, const float* __restrict__ cls) {
    int row = blockIdx.x;
    int b = row / LSEQ;
    int l = row - b * LSEQ;
    int tid = threadIdx.x;
    int st  = g_starts[b];
    int cnt = g_starts[b + 1] - st;
    float4 v = make_float4(0.f, 0.f, 0.f, 0.f);
    if (l == SSEQ) {
        v = ((const float4*)(cls + (size_t)b * D512))[tid];
    } else if (l < cnt) {
        v = ((const float4*)(x + (size_t)(st + l) * D512))[tid];
    }
    ((float4*)(g_xd + (size_t)row * D512))[tid] = v;
}

// ---------------- 3xBF16 tensor-core GEMM ----------------
// C = A(MxK) @ W(KxN) + bias [+res] [relu].
// fp32 split: x = hi(bf16) + lo(bf16); compute hh + lh + hl (drop ll ~2^-18).
// 128x128 tile, BK=16, 256 threads (8 warps of 64x32), mma.m16n8k16.bf16.

__device__ __forceinline__ void splitpair(float x, float y, unsigned& h, unsigned& l) {
    __nv_bfloat16 hx = __float2bfloat16_rn(x);
    __nv_bfloat16 hy = __float2bfloat16_rn(y);
    __nv_bfloat16 lx = __float2bfloat16_rn(x - __bfloat162float(hx));
    __nv_bfloat16 ly = __float2bfloat16_rn(y - __bfloat162float(hy));
    __nv_bfloat162 hh; hh.x = hx; hh.y = hy;   // low half = first (lower-k) element
    __nv_bfloat162 ll; ll.x = lx; ll.y = ly;
    h = *(unsigned*)&hh; l = *(unsigned*)&ll;
}
__device__ __forceinline__ void mma16(float* c, const unsigned* a, const unsigned* b) {
    asm volatile(
        "mma.sync.aligned.m16n8k16.row.col.f32.bf16.bf16.f32 "
        "{%0,%1,%2,%3}, {%4,%5,%6,%7}, {%8,%9}, {%0,%1,%2,%3};"
        : "+f"(c[0]), "+f"(c[1]), "+f"(c[2]), "+f"(c[3])
        : "r"(a[0]), "r"(a[1]), "r"(a[2]), "r"(a[3]), "r"(b[0]), "r"(b[1]));
}

#define ASTR 12                  // u32 stride per A row (8 pairs + pad4): conflict-free
#define ASZ  (128 * ASTR)        // 1536 u32 per plane
#define BSTR 136                 // u32 stride per B k'-row (128 n + pad8): conflict-free
#define BSZ  (8 * BSTR)          // 1088 u32 per plane
#define STG  (2 * ASZ + 2 * BSZ) // 5248 u32 per stage
#define GEMM_SMEM_U32 (2 * STG)  // 10496 u32 = 41984 B (static)

template<bool RELU, bool HASRES>
__device__ __forceinline__ void gemm_body(
    const float* __restrict__ A, const float* __restrict__ W,
    const float* __restrict__ bias, const float* __restrict__ res,
    float* __restrict__ C, int M, int N, int K, unsigned* smu)
{
    int tid  = threadIdx.x;
    int lane = tid & 31;
    int warp = tid >> 5;
    int wm = warp >> 2;          // 0..1
    int wn = warp & 3;           // 0..3
    int brow = blockIdx.y * 128;
    int bcol = blockIdx.x * 128;

    float acc[4][4][4];
#pragma unroll
    for (int mt = 0; mt < 4; mt++)
#pragma unroll
        for (int nt = 0; nt < 4; nt++)
#pragma unroll
            for (int i = 0; i < 4; i++) acc[mt][nt][i] = 0.f;

    // staging coords: A: 2 threads/row, 2 float4 each; B: pair-rows (2k) x 4-col groups
    int arow = tid >> 1, ahalf = tid & 1;     // row 0..127, k-half 0/1
    int bpr  = tid >> 5, bcg = tid & 31;      // k'-pair-row 0..7, col-group 0..31
    int agr  = brow + arow;
    bool aok = agr < M;
    const float* Ap = A + (size_t)(aok ? agr : 0) * K + ahalf * 8;

    int nchunks = K >> 4;
    float4 av0, av1, bw0, bw1;

    // helper lambdas (inlined)
    auto stage_store = [&](unsigned* base, float4 a0, float4 a1, float4 w0, float4 w1) {
        unsigned* AsHi = base;            unsigned* AsLo = base + ASZ;
        unsigned* BsHi = base + 2 * ASZ;  unsigned* BsLo = base + 2 * ASZ + BSZ;
        unsigned h0,l0,h1,l1,h2,l2,h3,l3;
        splitpair(a0.x, a0.y, h0, l0); splitpair(a0.z, a0.w, h1, l1);
        splitpair(a1.x, a1.y, h2, l2); splitpair(a1.z, a1.w, h3, l3);
        *(uint4*)(AsHi + arow * ASTR + ahalf * 4) = make_uint4(h0, h1, h2, h3);
        *(uint4*)(AsLo + arow * ASTR + ahalf * 4) = make_uint4(l0, l1, l2, l3);
        // B pairs along k: {W[2k'][n], W[2k'+1][n]}
        splitpair(w0.x, w1.x, h0, l0); splitpair(w0.y, w1.y, h1, l1);
        splitpair(w0.z, w1.z, h2, l2); splitpair(w0.w, w1.w, h3, l3);
        *(uint4*)(BsHi + bpr * BSTR + bcg * 4) = make_uint4(h0, h1, h2, h3);
        *(uint4*)(BsLo + bpr * BSTR + bcg * 4) = make_uint4(l0, l1, l2, l3);
    };

    // prologue: stage chunk 0
    {
        av0 = aok ? *(const float4*)(Ap)     : make_float4(0,0,0,0);
        av1 = aok ? *(const float4*)(Ap + 4) : make_float4(0,0,0,0);
        bw0 = *(const float4*)(W + (size_t)(2 * bpr)     * N + bcol + bcg * 4);
        bw1 = *(const float4*)(W + (size_t)(2 * bpr + 1) * N + bcol + bcg * 4);
        stage_store(smu, av0, av1, bw0, bw1);
    }

    int r = lane >> 2, cl = lane & 3;
    for (int ch = 0; ch < nchunks; ch++) {
        __syncthreads();
        if (ch + 1 < nchunks) {
            int k0 = (ch + 1) << 4;
            av0 = aok ? *(const float4*)(Ap + k0)     : make_float4(0,0,0,0);
            av1 = aok ? *(const float4*)(Ap + k0 + 4) : make_float4(0,0,0,0);
            bw0 = *(const float4*)(W + (size_t)(k0 + 2 * bpr)     * N + bcol + bcg * 4);
            bw1 = *(const float4*)(W + (size_t)(k0 + 2 * bpr + 1) * N + bcol + bcg * 4);
        }
        unsigned* base = smu + (ch & 1) * STG;
        unsigned* AsHi = base;            unsigned* AsLo = base + ASZ;
        unsigned* BsHi = base + 2 * ASZ;  unsigned* BsLo = base + 2 * ASZ + BSZ;

        unsigned ah[4][4], al[4][4], bh[4][2], bl[4][2];
#pragma unroll
        for (int mt = 0; mt < 4; mt++) {
            int o = (wm * 64 + mt * 16 + r) * ASTR + cl;
            ah[mt][0] = AsHi[o];           ah[mt][1] = AsHi[o + 8 * ASTR];
            ah[mt][2] = AsHi[o + 4];       ah[mt][3] = AsHi[o + 8 * ASTR + 4];
            al[mt][0] = AsLo[o];           al[mt][1] = AsLo[o + 8 * ASTR];
            al[mt][2] = AsLo[o + 4];       al[mt][3] = AsLo[o + 8 * ASTR + 4];
        }
#pragma unroll
        for (int nt = 0; nt < 4; nt++) {
            int o = cl * BSTR + wn * 32 + nt * 8 + r;
            bh[nt][0] = BsHi[o];  bh[nt][1] = BsHi[o + 4 * BSTR];
            bl[nt][0] = BsLo[o];  bl[nt][1] = BsLo[o + 4 * BSTR];
        }
#pragma unroll
        for (int mt = 0; mt < 4; mt++)
#pragma unroll
            for (int nt = 0; nt < 4; nt++) {
                mma16(acc[mt][nt], ah[mt], bh[nt]);   // hi*hi
                mma16(acc[mt][nt], al[mt], bh[nt]);   // lo*hi
                mma16(acc[mt][nt], ah[mt], bl[nt]);   // hi*lo
            }
        __syncthreads();
        if (ch + 1 < nchunks)
            stage_store(smu + ((ch + 1) & 1) * STG, av0, av1, bw0, bw1);
    }

    // epilogue
#pragma unroll
    for (int mt = 0; mt < 4; mt++) {
        int row0 = brow + wm * 64 + mt * 16 + r;
        int row1 = row0 + 8;
#pragma unroll
        for (int nt = 0; nt < 4; nt++) {
            int col = bcol + wn * 32 + nt * 8 + cl * 2;
            float2 bb = *(const float2*)(bias + col);
            const float* c = acc[mt][nt];
            if (row0 < M) {
                float v0 = c[0] + bb.x, v1 = c[1] + bb.y;
                if (HASRES) {
                    float2 rv = *(const float2*)(res + (size_t)row0 * N + col);
                    v0 += rv.x; v1 += rv.y;
                }
                if (RELU) { v0 = fmaxf(v0, 0.f); v1 = fmaxf(v1, 0.f); }
                *(float2*)(C + (size_t)row0 * N + col) = make_float2(v0, v1);
            }
            if (row1 < M) {
                float v0 = c[2] + bb.x, v1 = c[3] + bb.y;
                if (HASRES) {
                    float2 rv = *(const float2*)(res + (size_t)row1 * N + col);
                    v0 += rv.x; v1 += rv.y;
                }
                if (RELU) { v0 = fmaxf(v0, 0.f); v1 = fmaxf(v1, 0.f); }
                *(float2*)(C + (size_t)row1 * N + col) = make_float2(v0, v1);
            }
        }
    }
}

template<bool RELU, int ABUF, int CBUF, int RBUF>
__global__ void __launch_bounds__(256) k_mma(
    const float* __restrict__ W, const float* __restrict__ bias,
    int M, int N, int K)
{
    __shared__ unsigned smu[GEMM_SMEM_U32];
    const float* res = (RBUF >= 0) ? gbuf<(RBUF >= 0) ? RBUF : 0>() : (const float*)0;
    gemm_body<RELU, (RBUF >= 0)>(gbuf<ABUF>(), W, bias, res, gbuf<CBUF>(), M, N, K, smu);
}

// fused QKV: gridDim.z = 3 selects weight/bias/output
__global__ void __launch_bounds__(256) k_mma_qkv(
    const float* __restrict__ Wq, const float* __restrict__ bq,
    const float* __restrict__ Wk, const float* __restrict__ bk,
    const float* __restrict__ Wv, const float* __restrict__ bv,
    int M)
{
    __shared__ unsigned smu[GEMM_SMEM_U32];
    const float* W; const float* bias; float* C;
    if (blockIdx.z == 0)      { W = Wq; bias = bq; C = g_q; }
    else if (blockIdx.z == 1) { W = Wk; bias = bk; C = g_k; }
    else                      { W = Wv; bias = bv; C = g_v; }
    gemm_body<false, false>(g_xd, W, bias, (const float*)0, C, M, 512, 512, smu);
}

// ---------------- fused flash attention (per (b, h, q-tile of 64)) ----------------
__global__ void __launch_bounds__(64) k_attn() {
    __shared__ float KV [64][64];
    __shared__ float Ssh[64][65];
    int b  = blockIdx.z;
    int h  = blockIdx.y;
    int qt = blockIdx.x;
    int tid = threadIdx.x;
    int q = qt * 64 + tid;
    int cnt = g_starts[b + 1] - g_starts[b];
    if (!((qt * 64 < cnt) || (qt == 12))) return;   // dead q-tile
    bool qok = q < LSEQ;

    const float* qp = g_q + ((size_t)(b * LSEQ + (qok ? q : 0)) * D512) + h * DH;
    float qr[64];
#pragma unroll
    for (int i = 0; i < 16; i++) {
        float4 t = ((const float4*)qp)[i];
        qr[4*i] = t.x; qr[4*i+1] = t.y; qr[4*i+2] = t.z; qr[4*i+3] = t.w;
    }
    float o[64];
#pragma unroll
    for (int d = 0; d < 64; d++) o[d] = 0.f;
    float m = -1e30f, lsum = 0.f;

    for (int kt = 0; kt < 13; kt++) {
        if (!((kt * 64 < cnt) || (kt == 12))) continue;   // zero-prob k-chunk
        int kg = kt * 64 + tid;
        int kr = (kg < LSEQ) ? kg : (LSEQ - 1);
        const float* kp = g_k + ((size_t)(b * LSEQ + kr) * D512) + h * DH;
#pragma unroll
        for (int i = 0; i < 16; i++) ((float4*)KV[tid])[i] = ((const float4*)kp)[i];
        __syncthreads();

        float cmax = -1e30f;
        for (int k = 0; k < 64; k++) {
            float s = 0.f;
#pragma unroll
            for (int d = 0; d < 64; d++) s = fmaf(qr[d], KV[k][d], s);
            int kglob = kt * 64 + k;
            bool kvalid = (kglob < cnt) || (kglob == SSEQ);
            s = (kglob < LSEQ) ? (s * 0.125f + (kvalid ? 0.f : -1000000000.0f)) : -1e30f;
            Ssh[tid][k] = s;
            cmax = fmaxf(cmax, s);
        }
        __syncthreads();

        const float* vp = g_v + ((size_t)(b * LSEQ + kr) * D512) + h * DH;
#pragma unroll
        for (int i = 0; i < 16; i++) ((float4*)KV[tid])[i] = ((const float4*)vp)[i];
        __syncthreads();

        float mnew = fmaxf(m, cmax);
        float corr = __expf(m - mnew);
        m = mnew;
        lsum *= corr;
#pragma unroll
        for (int d = 0; d < 64; d++) o[d] *= corr;
        for (int k = 0; k < 64; k++) {
            float p = __expf(Ssh[tid][k] - m);
            lsum += p;
#pragma unroll
            for (int d = 0; d < 64; d++) o[d] = fmaf(p, KV[k][d], o[d]);
        }
        __syncthreads();
    }

    if (qok) {
        float inv = 1.f / lsum;
        float* op = g_at + ((size_t)(b * LSEQ + q) * D512) + h * DH;
#pragma unroll
        for (int i = 0; i < 16; i++) {
            float4 t = make_float4(o[4*i] * inv, o[4*i+1] * inv, o[4*i+2] * inv, o[4*i+3] * inv);
            ((float4*)op)[i] = t;
        }
    }
}

// ---------------- LayerNorm ----------------
__device__ __forceinline__ void row_ln(const float* __restrict__ src,
                                       const float* __restrict__ gam,
                                       const float* __restrict__ bet,
                                       float* __restrict__ dst) {
    int tid = threadIdx.x;
    float4 v = ((const float4*)src)[tid];
    float s  = v.x + v.y + v.z + v.w;
    float ss = v.x*v.x + v.y*v.y + v.z*v.z + v.w*v.w;
#pragma unroll
    for (int off = 16; off; off >>= 1) {
        s  += __shfl_xor_sync(0xffffffffu, s,  off);
        ss += __shfl_xor_sync(0xffffffffu, ss, off);
    }
    __shared__ float sh[4][2];
    int w = tid >> 5;
    if ((tid & 31) == 0) { sh[w][0] = s; sh[w][1] = ss; }
    __syncthreads();
    s  = sh[0][0] + sh[1][0] + sh[2][0] + sh[3][0];
    ss = sh[0][1] + sh[1][1] + sh[2][1] + sh[3][1];
    float mean = s * (1.f / 512.f);
    float var  = ss * (1.f / 512.f) - mean * mean;
    float rr = rsqrtf(var + 1e-5f);
    float4 gg = ((const float4*)gam)[tid];
    float4 bb = ((const float4*)bet)[tid];
    float4 out;
    out.x = (v.x - mean) * rr * gg.x + bb.x;
    out.y = (v.y - mean) * rr * gg.y + bb.y;
    out.z = (v.z - mean) * rr * gg.z + bb.z;
    out.w = (v.w - mean) * rr * gg.w + bb.w;
    ((float4*)dst)[tid] = out;
}

__global__ void k_gather_ln(const int* __restrict__ batch,
                            const float* __restrict__ gam, const float* __restrict__ bet,
                            int N) {
    int row = blockIdx.x;
    const float* src;
    if (row < N) {
        int b = batch[row];
        int p = row - g_starts[b];
        src = g_ao + ((size_t)(b * LSEQ + p)) * D512;
    } else {
        int b = row - N;
        src = g_ao + ((size_t)(b * LSEQ + SSEQ)) * D512;
    }
    row_ln(src, gam, bet, g_hn + (size_t)row * D512);
}

__global__ void k_ln(const float* __restrict__ gam, const float* __restrict__ bet,
                     float* __restrict__ out) {
    int row = blockIdx.x;
    row_ln(g_f + (size_t)row * D512, gam, bet, out + (size_t)row * D512);
}

// ---------------- launch ----------------
extern "C" void kernel_launch(void* const* d_in, const int* in_sizes, int n_in,
                              void* d_out, int out_size) {
    const float* x     = (const float*)d_in[0];
    const int*   batch = (const int*)  d_in[1];
    const float* cls   = (const float*)d_in[2];
    const float* Wq = (const float*)d_in[3];  const float* bq = (const float*)d_in[4];
    const float* Wk = (const float*)d_in[5];  const float* bk = (const float*)d_in[6];
    const float* Wv = (const float*)d_in[7];  const float* bv = (const float*)d_in[8];
    const float* Wo = (const float*)d_in[9];  const float* bo = (const float*)d_in[10];
    const float* W1 = (const float*)d_in[11]; const float* b1 = (const float*)d_in[12];
    const float* W2 = (const float*)d_in[13]; const float* b2 = (const float*)d_in[14];
    const float* g0 = (const float*)d_in[15]; const float* be0 = (const float*)d_in[16];
    const float* ga1 = (const float*)d_in[17]; const float* be1 = (const float*)d_in[18];

    int N = in_sizes[0] / D512;      // 16384
    int B = in_sizes[2] / D512;      // 32
    int M1 = B * LSEQ;               // 24608
    int M2 = N + B;                  // 16416

    k_starts<<<1, 64>>>(batch, N, B);
    k_build_xd<<<M1, 128>>>(x, cls);

    dim3 gqkv3(512 / 128, (M1 + 127) / 128, 3);
    k_mma_qkv<<<gqkv3, 256>>>(Wq, bq, Wk, bk, Wv, bv, M1);

    k_attn<<<dim3(13, NH, B), 64>>>();

    dim3 gao(512 / 128, (M1 + 127) / 128);
    k_mma<false, BUF_AT, BUF_AO, BUF_XD><<<gao, 256>>>(Wo, bo, M1, 512, 512);

    k_gather_ln<<<M2, 128>>>(batch, g0, be0, N);

    dim3 gf1(1024 / 128, (M2 + 127) / 128);
    k_mma<true,  BUF_HN, BUF_T, -1><<<gf1, 256>>>(W1, b1, M2, 1024, 512);
    dim3 gf2(512 / 128, (M2 + 127) / 128);
    k_mma<false, BUF_T, BUF_F, BUF_HN><<<gf2, 256>>>(W2, b2, M2, 512, 1024);

    k_ln<<<M2, 128>>>(ga1, be1, (float*)d_out);
}

// round 6
// speedup vs baseline: 3.8077x; 1.9708x over previous
#include <cuda_runtime.h>
#include <cuda_bf16.h>
#include <math.h>

// ---------------- problem constants ----------------
#define D512 512
#define NH   8
#define DH   64
#define SSEQ 768
#define LSEQ 769
#define BMAX 32
#define NMAX 16384
#define MROWS (NMAX + BMAX)   // 16416

// ---------------- scratch ----------------
__device__ __align__(256) float g_xc[MROWS * D512];     // compact [x; CLS]
__device__ __align__(256) float g_q [MROWS * D512];
__device__ __align__(256) float g_k [MROWS * D512];
__device__ __align__(256) float g_v [MROWS * D512];
__device__ __align__(256) float g_at[MROWS * D512];
__device__ __align__(256) float g_ao[MROWS * D512];
__device__ __align__(256) float g_hn[MROWS * D512];
__device__ __align__(256) float g_t [MROWS * 1024];
__device__ __align__(256) float g_f [MROWS * D512];
__device__ int g_starts[BMAX + 1];

#define BUF_XC 0
#define BUF_Q  1
#define BUF_K  2
#define BUF_V  3
#define BUF_AT 4
#define BUF_AO 5
#define BUF_HN 6
#define BUF_T  7
#define BUF_F  8
template<int ID> __device__ __forceinline__ float* gbuf() {
    if constexpr (ID == BUF_XC) return g_xc;
    else if constexpr (ID == BUF_Q)  return g_q;
    else if constexpr (ID == BUF_K)  return g_k;
    else if constexpr (ID == BUF_V)  return g_v;
    else if constexpr (ID == BUF_AT) return g_at;
    else if constexpr (ID == BUF_AO) return g_ao;
    else if constexpr (ID == BUF_HN) return g_hn;
    else if constexpr (ID == BUF_T)  return g_t;
    else return g_f;
}

// ---------------- starts ----------------
__global__ void k_starts(const int* __restrict__ batch, int N, int B) {
    int b = threadIdx.x;
    if (b > B) return;
    int lo = 0, hi = N;
    while (lo < hi) {
        int mid = (lo + hi) >> 1;
        if (batch[mid] < b) lo = mid + 1; else hi = mid;
    }
    g_starts[b] = lo;
}

// ---------------- build compact input [x; CLS] ----------------
__global__ void k_xc(const float* __restrict__ x, const float* __restrict__ cls, int N) {
    int row = blockIdx.x;
    int tid = threadIdx.x;
    const float* src = (row < N) ? (x + (size_t)row * D512)
                                 : (cls + (size_t)(row - N) * D512);
    ((float4*)(g_xc + (size_t)row * D512))[tid] = ((const float4*)src)[tid];
}

// ---------------- bf16 split helpers + MMA ----------------
__device__ __forceinline__ void splitpair(float x, float y, unsigned& h, unsigned& l) {
    __nv_bfloat16 hx = __float2bfloat16_rn(x);
    __nv_bfloat16 hy = __float2bfloat16_rn(y);
    __nv_bfloat16 lx = __float2bfloat16_rn(x - __bfloat162float(hx));
    __nv_bfloat16 ly = __float2bfloat16_rn(y - __bfloat162float(hy));
    __nv_bfloat162 hh; hh.x = hx; hh.y = hy;
    __nv_bfloat162 ll; ll.x = lx; ll.y = ly;
    h = *(unsigned*)&hh; l = *(unsigned*)&ll;
}
__device__ __forceinline__ void mma16(float* c, const unsigned* a, const unsigned* b) {
    asm volatile(
        "mma.sync.aligned.m16n8k16.row.col.f32.bf16.bf16.f32 "
        "{%0,%1,%2,%3}, {%4,%5,%6,%7}, {%8,%9}, {%0,%1,%2,%3};"
        : "+f"(c[0]), "+f"(c[1]), "+f"(c[2]), "+f"(c[3])
        : "r"(a[0]), "r"(a[1]), "r"(a[2]), "r"(a[3]), "r"(b[0]), "r"(b[1]));
}

// ---------------- 3xBF16 GEMM (unchanged from R4; proven) ----------------
#define ASTR 12
#define ASZ  (128 * ASTR)
#define BSTR 136
#define BSZ  (8 * BSTR)
#define STG  (2 * ASZ + 2 * BSZ)
#define GEMM_SMEM_U32 (2 * STG)

template<bool RELU, bool HASRES>
__device__ __forceinline__ void gemm_body(
    const float* __restrict__ A, const float* __restrict__ W,
    const float* __restrict__ bias, const float* __restrict__ res,
    float* __restrict__ C, int M, int N, int K, unsigned* smu)
{
    int tid  = threadIdx.x;
    int lane = tid & 31;
    int warp = tid >> 5;
    int wm = warp >> 2;
    int wn = warp & 3;
    int brow = blockIdx.y * 128;
    int bcol = blockIdx.x * 128;

    float acc[4][4][4];
#pragma unroll
    for (int mt = 0; mt < 4; mt++)
#pragma unroll
        for (int nt = 0; nt < 4; nt++)
#pragma unroll
            for (int i = 0; i < 4; i++) acc[mt][nt][i] = 0.f;

    int arow = tid >> 1, ahalf = tid & 1;
    int bpr  = tid >> 5, bcg = tid & 31;
    int agr  = brow + arow;
    bool aok = agr < M;
    const float* Ap = A + (size_t)(aok ? agr : 0) * K + ahalf * 8;

    int nchunks = K >> 4;
    float4 av0, av1, bw0, bw1;

    auto stage_store = [&](unsigned* base, float4 a0, float4 a1, float4 w0, float4 w1) {
        unsigned* AsHi = base;            unsigned* AsLo = base + ASZ;
        unsigned* BsHi = base + 2 * ASZ;  unsigned* BsLo = base + 2 * ASZ + BSZ;
        unsigned h0,l0,h1,l1,h2,l2,h3,l3;
        splitpair(a0.x, a0.y, h0, l0); splitpair(a0.z, a0.w, h1, l1);
        splitpair(a1.x, a1.y, h2, l2); splitpair(a1.z, a1.w, h3, l3);
        *(uint4*)(AsHi + arow * ASTR + ahalf * 4) = make_uint4(h0, h1, h2, h3);
        *(uint4*)(AsLo + arow * ASTR + ahalf * 4) = make_uint4(l0, l1, l2, l3);
        splitpair(w0.x, w1.x, h0, l0); splitpair(w0.y, w1.y, h1, l1);
        splitpair(w0.z, w1.z, h2, l2); splitpair(w0.w, w1.w, h3, l3);
        *(uint4*)(BsHi + bpr * BSTR + bcg * 4) = make_uint4(h0, h1, h2, h3);
        *(uint4*)(BsLo + bpr * BSTR + bcg * 4) = make_uint4(l0, l1, l2, l3);
    };

    {
        av0 = aok ? *(const float4*)(Ap)     : make_float4(0,0,0,0);
        av1 = aok ? *(const float4*)(Ap + 4) : make_float4(0,0,0,0);
        bw0 = *(const float4*)(W + (size_t)(2 * bpr)     * N + bcol + bcg * 4);
        bw1 = *(const float4*)(W + (size_t)(2 * bpr + 1) * N + bcol + bcg * 4);
        stage_store(smu, av0, av1, bw0, bw1);
    }

    int r = lane >> 2, cl = lane & 3;
    for (int ch = 0; ch < nchunks; ch++) {
        __syncthreads();
        if (ch + 1 < nchunks) {
            int k0 = (ch + 1) << 4;
            av0 = aok ? *(const float4*)(Ap + k0)     : make_float4(0,0,0,0);
            av1 = aok ? *(const float4*)(Ap + k0 + 4) : make_float4(0,0,0,0);
            bw0 = *(const float4*)(W + (size_t)(k0 + 2 * bpr)     * N + bcol + bcg * 4);
            bw1 = *(const float4*)(W + (size_t)(k0 + 2 * bpr + 1) * N + bcol + bcg * 4);
        }
        unsigned* base = smu + (ch & 1) * STG;
        unsigned* AsHi = base;            unsigned* AsLo = base + ASZ;
        unsigned* BsHi = base + 2 * ASZ;  unsigned* BsLo = base + 2 * ASZ + BSZ;

        unsigned ah[4][4], al[4][4], bh[4][2], bl[4][2];
#pragma unroll
        for (int mt = 0; mt < 4; mt++) {
            int o = (wm * 64 + mt * 16 + r) * ASTR + cl;
            ah[mt][0] = AsHi[o];           ah[mt][1] = AsHi[o + 8 * ASTR];
            ah[mt][2] = AsHi[o + 4];       ah[mt][3] = AsHi[o + 8 * ASTR + 4];
            al[mt][0] = AsLo[o];           al[mt][1] = AsLo[o + 8 * ASTR];
            al[mt][2] = AsLo[o + 4];       al[mt][3] = AsLo[o + 8 * ASTR + 4];
        }
#pragma unroll
        for (int nt = 0; nt < 4; nt++) {
            int o = cl * BSTR + wn * 32 + nt * 8 + r;
            bh[nt][0] = BsHi[o];  bh[nt][1] = BsHi[o + 4 * BSTR];
            bl[nt][0] = BsLo[o];  bl[nt][1] = BsLo[o + 4 * BSTR];
        }
#pragma unroll
        for (int mt = 0; mt < 4; mt++)
#pragma unroll
            for (int nt = 0; nt < 4; nt++) {
                mma16(acc[mt][nt], ah[mt], bh[nt]);
                mma16(acc[mt][nt], al[mt], bh[nt]);
                mma16(acc[mt][nt], ah[mt], bl[nt]);
            }
        __syncthreads();
        if (ch + 1 < nchunks)
            stage_store(smu + ((ch + 1) & 1) * STG, av0, av1, bw0, bw1);
    }

#pragma unroll
    for (int mt = 0; mt < 4; mt++) {
        int row0 = brow + wm * 64 + mt * 16 + r;
        int row1 = row0 + 8;
#pragma unroll
        for (int nt = 0; nt < 4; nt++) {
            int col = bcol + wn * 32 + nt * 8 + cl * 2;
            float2 bb = *(const float2*)(bias + col);
            const float* c = acc[mt][nt];
            if (row0 < M) {
                float v0 = c[0] + bb.x, v1 = c[1] + bb.y;
                if (HASRES) {
                    float2 rv = *(const float2*)(res + (size_t)row0 * N + col);
                    v0 += rv.x; v1 += rv.y;
                }
                if (RELU) { v0 = fmaxf(v0, 0.f); v1 = fmaxf(v1, 0.f); }
                *(float2*)(C + (size_t)row0 * N + col) = make_float2(v0, v1);
            }
            if (row1 < M) {
                float v0 = c[2] + bb.x, v1 = c[3] + bb.y;
                if (HASRES) {
                    float2 rv = *(const float2*)(res + (size_t)row1 * N + col);
                    v0 += rv.x; v1 += rv.y;
                }
                if (RELU) { v0 = fmaxf(v0, 0.f); v1 = fmaxf(v1, 0.f); }
                *(float2*)(C + (size_t)row1 * N + col) = make_float2(v0, v1);
            }
        }
    }
}

template<bool RELU, int ABUF, int CBUF, int RBUF>
__global__ void __launch_bounds__(256) k_mma(
    const float* __restrict__ W, const float* __restrict__ bias,
    int M, int N, int K)
{
    __shared__ unsigned smu[GEMM_SMEM_U32];
    const float* res = (RBUF >= 0) ? gbuf<(RBUF >= 0) ? RBUF : 0>() : (const float*)0;
    gemm_body<RELU, (RBUF >= 0)>(gbuf<ABUF>(), W, bias, res, gbuf<CBUF>(), M, N, K, smu);
}

__global__ void __launch_bounds__(256) k_mma_qkv(
    const float* __restrict__ Wq, const float* __restrict__ bq,
    const float* __restrict__ Wk, const float* __restrict__ bk,
    const float* __restrict__ Wv, const float* __restrict__ bv,
    int M)
{
    __shared__ unsigned smu[GEMM_SMEM_U32];
    const float* W; const float* bias; float* C;
    if (blockIdx.z == 0)      { W = Wq; bias = bq; C = g_q; }
    else if (blockIdx.z == 1) { W = Wk; bias = bk; C = g_k; }
    else                      { W = Wv; bias = bv; C = g_v; }
    gemm_body<false, false>(g_xc, W, bias, (const float*)0, C, M, 512, 512, smu);
}

// ---------------- tensor-core flash attention ----------------
// block = (b, h, q-tile of 64); 128 threads = 4 warps, 16 q-rows each.
// Compact rows: idx<cnt -> starts[b]+idx ; idx>=cnt -> CLS row N+b (clamp-safe).
#define AST 36   // u32 stride (32 data + 4 pad): conflict-free (4*row+col mod 32)

__global__ void __launch_bounds__(128) k_attn_mma(int N) {
    __shared__ unsigned KsHi[64*AST], KsLo[64*AST];
    __shared__ unsigned VtHi[64*AST], VtLo[64*AST];
    int b = blockIdx.z, h = blockIdx.y, qt = blockIdx.x;
    int st = g_starts[b];
    int cnt = g_starts[b + 1] - st;
    int Lb = cnt + 1;
    if (qt * 64 >= Lb) return;
    int tid = threadIdx.x, lane = tid & 31, warp = tid >> 5;
    int lr = lane >> 2, lc = lane & 3;

    // ---- stage Q tile into Ks buffers, extract A-frags, then free ----
    {
        int r = tid >> 1, half = tid & 1;
        int qi = qt * 64 + r;
        int grow = (qi < cnt) ? st + qi : N + b;
        const float* qp = g_q + (size_t)grow * D512 + h * DH + half * 32;
        unsigned hh[16], ll[16];
#pragma unroll
        for (int j = 0; j < 8; j++) {
            float4 f = ((const float4*)qp)[j];
            splitpair(f.x, f.y, hh[2*j],   ll[2*j]);
            splitpair(f.z, f.w, hh[2*j+1], ll[2*j+1]);
        }
        int base = r * AST + half * 16;
#pragma unroll
        for (int i = 0; i < 4; i++) {
            *(uint4*)(KsHi + base + 4*i) = make_uint4(hh[4*i], hh[4*i+1], hh[4*i+2], hh[4*i+3]);
            *(uint4*)(KsLo + base + 4*i) = make_uint4(ll[4*i], ll[4*i+1], ll[4*i+2], ll[4*i+3]);
        }
    }
    __syncthreads();
    unsigned qh[4][4], qlo[4][4];
    {
        int rq = warp * 16 + lr;
#pragma unroll
        for (int ks = 0; ks < 4; ks++) {
            int c0 = ks * 8 + lc;
            qh[ks][0]  = KsHi[rq*AST + c0];      qh[ks][1]  = KsHi[(rq+8)*AST + c0];
            qh[ks][2]  = KsHi[rq*AST + c0 + 4];  qh[ks][3]  = KsHi[(rq+8)*AST + c0 + 4];
            qlo[ks][0] = KsLo[rq*AST + c0];      qlo[ks][1] = KsLo[(rq+8)*AST + c0];
            qlo[ks][2] = KsLo[rq*AST + c0 + 4];  qlo[ks][3] = KsLo[(rq+8)*AST + c0 + 4];
        }
    }
    __syncthreads();

    float m0 = -1e30f, m1 = -1e30f, l0 = 0.f, l1 = 0.f;
    float o[8][4];
#pragma unroll
    for (int nt = 0; nt < 8; nt++)
#pragma unroll
        for (int i = 0; i < 4; i++) o[nt][i] = 0.f;

    int nch = (Lb + 63) >> 6;
    for (int kt = 0; kt < nch; kt++) {
        // K chunk: rows = keys, layout [key][dim-pair]
        {
            int r = tid >> 1, half = tid & 1;
            int ki = kt * 64 + r;
            int grow = (ki < cnt) ? st + ki : N + b;
            const float* kp = g_k + (size_t)grow * D512 + h * DH + half * 32;
            unsigned hh[16], ll[16];
#pragma unroll
            for (int j = 0; j < 8; j++) {
                float4 f = ((const float4*)kp)[j];
                splitpair(f.x, f.y, hh[2*j],   ll[2*j]);
                splitpair(f.z, f.w, hh[2*j+1], ll[2*j+1]);
            }
            int base = r * AST + half * 16;
#pragma unroll
            for (int i = 0; i < 4; i++) {
                *(uint4*)(KsHi + base + 4*i) = make_uint4(hh[4*i], hh[4*i+1], hh[4*i+2], hh[4*i+3]);
                *(uint4*)(KsLo + base + 4*i) = make_uint4(ll[4*i], ll[4*i+1], ll[4*i+2], ll[4*i+3]);
            }
        }
        // V chunk transposed: [dim][key-pair]; warp w covers dims 16w..16w+15, lane = keypair
        {
            int k0i = kt * 64 + 2 * lane;
            int gr0 = (k0i     < cnt) ? st + k0i     : N + b;
            int gr1 = (k0i + 1 < cnt) ? st + k0i + 1 : N + b;
            const float* v0 = g_v + (size_t)gr0 * D512 + h * DH + warp * 16;
            const float* v1 = g_v + (size_t)gr1 * D512 + h * DH + warp * 16;
#pragma unroll
            for (int j = 0; j < 4; j++) {
                float4 f0 = ((const float4*)v0)[j];
                float4 f1 = ((const float4*)v1)[j];
                int d = warp * 16 + 4 * j;
                unsigned hx, lx;
                splitpair(f0.x, f1.x, hx, lx); VtHi[(d+0)*AST + lane] = hx; VtLo[(d+0)*AST + lane] = lx;
                splitpair(f0.y, f1.y, hx, lx); VtHi[(d+1)*AST + lane] = hx; VtLo[(d+1)*AST + lane] = lx;
                splitpair(f0.z, f1.z, hx, lx); VtHi[(d+2)*AST + lane] = hx; VtLo[(d+2)*AST + lane] = lx;
                splitpair(f0.w, f1.w, hx, lx); VtHi[(d+3)*AST + lane] = hx; VtLo[(d+3)*AST + lane] = lx;
            }
        }
        __syncthreads();

        // S = Q K^T (3-term split)
        float s[8][4];
#pragma unroll
        for (int nt = 0; nt < 8; nt++) {
            s[nt][0] = s[nt][1] = s[nt][2] = s[nt][3] = 0.f;
#pragma unroll
            for (int ks = 0; ks < 4; ks++) {
                int ko = (nt * 8 + lr) * AST + ks * 8 + lc;
                unsigned bh[2] = {KsHi[ko], KsHi[ko + 4]};
                unsigned bl[2] = {KsLo[ko], KsLo[ko + 4]};
                mma16(s[nt], qh[ks],  bh);
                mma16(s[nt], qlo[ks], bh);
                mma16(s[nt], qh[ks],  bl);
            }
        }
        // scale + tail mask (keys >= Lb excluded exactly, matching exp(-1e9-m)=0)
        int cb = kt * 64 + 2 * lc;
#pragma unroll
        for (int nt = 0; nt < 8; nt++) {
            int c0 = cb + nt * 8, c1 = c0 + 1;
            bool v0 = c0 < Lb, v1 = c1 < Lb;
            s[nt][0] = v0 ? s[nt][0] * 0.125f : -1e30f;
            s[nt][1] = v1 ? s[nt][1] * 0.125f : -1e30f;
            s[nt][2] = v0 ? s[nt][2] * 0.125f : -1e30f;
            s[nt][3] = v1 ? s[nt][3] * 0.125f : -1e30f;
        }
        // row maxima (quad shuffle: lanes 4r..4r+3 share a row)
        float cm0 = -1e30f, cm1 = -1e30f;
#pragma unroll
        for (int nt = 0; nt < 8; nt++) {
            cm0 = fmaxf(cm0, fmaxf(s[nt][0], s[nt][1]));
            cm1 = fmaxf(cm1, fmaxf(s[nt][2], s[nt][3]));
        }
        cm0 = fmaxf(cm0, __shfl_xor_sync(0xffffffffu, cm0, 1));
        cm0 = fmaxf(cm0, __shfl_xor_sync(0xffffffffu, cm0, 2));
        cm1 = fmaxf(cm1, __shfl_xor_sync(0xffffffffu, cm1, 1));
        cm1 = fmaxf(cm1, __shfl_xor_sync(0xffffffffu, cm1, 2));
        float mn0 = fmaxf(m0, cm0), mn1 = fmaxf(m1, cm1);
        float corr0 = __expf(m0 - mn0), corr1 = __expf(m1 - mn1);
        m0 = mn0; m1 = mn1;

        // P = exp(S - m), pack to A-frags (hi/lo), row sums
        float sum0 = 0.f, sum1 = 0.f;
        unsigned pah[4][4], pal[4][4];
#pragma unroll
        for (int nt = 0; nt < 8; nt++) {
            float p0 = __expf(s[nt][0] - m0), p1 = __expf(s[nt][1] - m0);
            float p2 = __expf(s[nt][2] - m1), p3 = __expf(s[nt][3] - m1);
            sum0 += p0 + p1; sum1 += p2 + p3;
            unsigned h01, l01, h23, l23;
            splitpair(p0, p1, h01, l01);
            splitpair(p2, p3, h23, l23);
            int kq = nt >> 1, sl = (nt & 1) * 2;
            pah[kq][sl] = h01; pah[kq][sl + 1] = h23;
            pal[kq][sl] = l01; pal[kq][sl + 1] = l23;
        }
        sum0 += __shfl_xor_sync(0xffffffffu, sum0, 1);
        sum0 += __shfl_xor_sync(0xffffffffu, sum0, 2);
        sum1 += __shfl_xor_sync(0xffffffffu, sum1, 1);
        sum1 += __shfl_xor_sync(0xffffffffu, sum1, 2);
        l0 = l0 * corr0 + sum0;
        l1 = l1 * corr1 + sum1;
#pragma unroll
        for (int nt = 0; nt < 8; nt++) {
            o[nt][0] *= corr0; o[nt][1] *= corr0;
            o[nt][2] *= corr1; o[nt][3] *= corr1;
        }
        // O += P V (3-term split)
#pragma unroll
        for (int nt = 0; nt < 8; nt++) {
#pragma unroll
            for (int kq = 0; kq < 4; kq++) {
                int vo = (nt * 8 + lr) * AST + kq * 8 + lc;
                unsigned bh[2] = {VtHi[vo], VtHi[vo + 4]};
                unsigned bl[2] = {VtLo[vo], VtLo[vo + 4]};
                mma16(o[nt], pah[kq], bh);
                mma16(o[nt], pal[kq], bh);
                mma16(o[nt], pah[kq], bl);
            }
        }
        __syncthreads();
    }

    float inv0 = 1.f / l0, inv1 = 1.f / l1;
    int q0 = qt * 64 + warp * 16 + lr;
    int q1 = q0 + 8;
    if (q0 < Lb) {
        int gr = (q0 < cnt) ? st + q0 : N + b;
        float* op = g_at + (size_t)gr * D512 + h * DH + 2 * lc;
#pragma unroll
        for (int nt = 0; nt < 8; nt++)
            *(float2*)(op + nt * 8) = make_float2(o[nt][0] * inv0, o[nt][1] * inv0);
    }
    if (q1 < Lb) {
        int gr = (q1 < cnt) ? st + q1 : N + b;
        float* op = g_at + (size_t)gr * D512 + h * DH + 2 * lc;
#pragma unroll
        for (int nt = 0; nt < 8; nt++)
            *(float2*)(op + nt * 8) = make_float2(o[nt][2] * inv1, o[nt][3] * inv1);
    }
}

// ---------------- LayerNorm ----------------
__device__ __forceinline__ void row_ln(const float* __restrict__ src,
                                       const float* __restrict__ gam,
                                       const float* __restrict__ bet,
                                       float* __restrict__ dst) {
    int tid = threadIdx.x;
    float4 v = ((const float4*)src)[tid];
    float s  = v.x + v.y + v.z + v.w;
    float ss = v.x*v.x + v.y*v.y + v.z*v.z + v.w*v.w;
#pragma unroll
    for (int off = 16; off; off >>= 1) {
        s  += __shfl_xor_sync(0xffffffffu, s,  off);
        ss += __shfl_xor_sync(0xffffffffu, ss, off);
    }
    __shared__ float sh[4][2];
    int w = tid >> 5;
    if ((tid & 31) == 0) { sh[w][0] = s; sh[w][1] = ss; }
    __syncthreads();
    s  = sh[0][0] + sh[1][0] + sh[2][0] + sh[3][0];
    ss = sh[0][1] + sh[1][1] + sh[2][1] + sh[3][1];
    float mean = s * (1.f / 512.f);
    float var  = ss * (1.f / 512.f) - mean * mean;
    float rr = rsqrtf(var + 1e-5f);
    float4 gg = ((const float4*)gam)[tid];
    float4 bb = ((const float4*)bet)[tid];
    float4 out;
    out.x = (v.x - mean) * rr * gg.x + bb.x;
    out.y = (v.y - mean) * rr * gg.y + bb.y;
    out.z = (v.z - mean) * rr * gg.z + bb.z;
    out.w = (v.w - mean) * rr * gg.w + bb.w;
    ((float4*)dst)[tid] = out;
}

template<int SRC, int DST>
__global__ void k_ln_t(const float* __restrict__ gam, const float* __restrict__ bet,
                       float* __restrict__ out) {
    int row = blockIdx.x;
    float* dst = (DST >= 0) ? gbuf<(DST >= 0) ? DST : 0>() : out;
    row_ln(gbuf<SRC>() + (size_t)row * D512, gam, bet, dst + (size_t)row * D512);
}

// ---------------- launch ----------------
extern "C" void kernel_launch(void* const* d_in, const int* in_sizes, int n_in,
                              void* d_out, int out_size) {
    const float* x     = (const float*)d_in[0];
    const int*   batch = (const int*)  d_in[1];
    const float* cls   = (const float*)d_in[2];
    const float* Wq = (const float*)d_in[3];  const float* bq = (const float*)d_in[4];
    const float* Wk = (const float*)d_in[5];  const float* bk = (const float*)d_in[6];
    const float* Wv = (const float*)d_in[7];  const float* bv = (const float*)d_in[8];
    const float* Wo = (const float*)d_in[9];  const float* bo = (const float*)d_in[10];
    const float* W1 = (const float*)d_in[11]; const float* b1 = (const float*)d_in[12];
    const float* W2 = (const float*)d_in[13]; const float* b2 = (const float*)d_in[14];
    const float* g0 = (const float*)d_in[15]; const float* be0 = (const float*)d_in[16];
    const float* ga1 = (const float*)d_in[17]; const float* be1 = (const float*)d_in[18];

    int N = in_sizes[0] / D512;      // 16384
    int B = in_sizes[2] / D512;      // 32
    int M2 = N + B;                  // 16416 compact rows

    k_starts<<<1, 64>>>(batch, N, B);
    k_xc<<<M2, 128>>>(x, cls, N);

    dim3 gqkv3(512 / 128, (M2 + 127) / 128, 3);
    k_mma_qkv<<<gqkv3, 256>>>(Wq, bq, Wk, bk, Wv, bv, M2);

    k_attn_mma<<<dim3(13, NH, B), 128>>>(N);

    dim3 gao(512 / 128, (M2 + 127) / 128);
    k_mma<false, BUF_AT, BUF_AO, BUF_XC><<<gao, 256>>>(Wo, bo, M2, 512, 512);

    k_ln_t<BUF_AO, BUF_HN><<<M2, 128>>>(g0, be0, (float*)0);

    dim3 gf1(1024 / 128, (M2 + 127) / 128);
    k_mma<true,  BUF_HN, BUF_T, -1><<<gf1, 256>>>(W1, b1, M2, 1024, 512);
    dim3 gf2(512 / 128, (M2 + 127) / 128);
    k_mma<false, BUF_T, BUF_F, BUF_HN><<<gf2, 256>>>(W2, b2, M2, 512, 1024);

    k_ln_t<BUF_F, -1><<<M2, 128>>>(ga1, be1, (float*)d_out);
}

// round 7
// speedup vs baseline: 4.4252x; 1.1622x over previous
#include <cuda_runtime.h>
#include <cuda_bf16.h>
#include <math.h>

// ---------------- problem constants ----------------
#define D512 512
#define NH   8
#define DH   64
#define BMAX 32
#define NMAX 16384
#define MROWS (NMAX + BMAX)   // 16416

// ---------------- fp32 scratch ----------------
__device__ __align__(256) float g_xc[MROWS * D512];
__device__ __align__(256) float g_q [MROWS * D512];
__device__ __align__(256) float g_k [MROWS * D512];
__device__ __align__(256) float g_v [MROWS * D512];
__device__ __align__(256) float g_ao[MROWS * D512];
__device__ __align__(256) float g_hn[MROWS * D512];
__device__ __align__(256) float g_f [MROWS * D512];
__device__ int g_starts[BMAX + 1];

// ---------------- bf16 split planes (u32 = 2 bf16, low half = even index) ----------------
// A-type planes: [M][K/2] u32 (natural bf16 row-major)
__device__ __align__(256) unsigned g_xch[MROWS * 256], g_xcl[MROWS * 256];
__device__ __align__(256) unsigned g_ath[MROWS * 256], g_atl[MROWS * 256];
__device__ __align__(256) unsigned g_hnh[MROWS * 256], g_hnl[MROWS * 256];
__device__ __align__(256) unsigned g_th [MROWS * 512], g_tl [MROWS * 512];
// weight planes, pre-paired along k: u32 at [k2*N + n] = {W[2k2][n], W[2k2+1][n]}
#define WQ_OFF 0
#define WK_OFF 131072
#define WV_OFF 262144
#define WO_OFF 393216
#define W1_OFF 524288
#define W2_OFF 786432
#define WTOT   1048576
__device__ __align__(256) unsigned g_wh[WTOT], g_wl[WTOT];

// ---------------- helpers ----------------
__device__ __forceinline__ void splitpair(float x, float y, unsigned& h, unsigned& l) {
    __nv_bfloat16 hx = __float2bfloat16_rn(x);
    __nv_bfloat16 hy = __float2bfloat16_rn(y);
    __nv_bfloat16 lx = __float2bfloat16_rn(x - __bfloat162float(hx));
    __nv_bfloat16 ly = __float2bfloat16_rn(y - __bfloat162float(hy));
    __nv_bfloat162 hh; hh.x = hx; hh.y = hy;
    __nv_bfloat162 ll; ll.x = lx; ll.y = ly;
    h = *(unsigned*)&hh; l = *(unsigned*)&ll;
}
__device__ __forceinline__ void mma16(float* c, const unsigned* a, const unsigned* b) {
    asm volatile(
        "mma.sync.aligned.m16n8k16.row.col.f32.bf16.bf16.f32 "
        "{%0,%1,%2,%3}, {%4,%5,%6,%7}, {%8,%9}, {%0,%1,%2,%3};"
        : "+f"(c[0]), "+f"(c[1]), "+f"(c[2]), "+f"(c[3])
        : "r"(a[0]), "r"(a[1]), "r"(a[2]), "r"(a[3]), "r"(b[0]), "r"(b[1]));
}
__device__ __forceinline__ void ldm4(unsigned* d, unsigned a) {
    asm volatile("ldmatrix.sync.aligned.m8n8.x4.shared.b16 {%0,%1,%2,%3}, [%4];"
        : "=r"(d[0]), "=r"(d[1]), "=r"(d[2]), "=r"(d[3]) : "r"(a));
}
__device__ __forceinline__ void cpa16(unsigned dst, const void* src, int sz) {
    asm volatile("cp.async.cg.shared.global [%0], [%1], 16, %2;"
        :: "r"(dst), "l"(src), "r"(sz));
}
#define CP_COMMIT() asm volatile("cp.async.commit_group;")
#define CP_WAIT0()  asm volatile("cp.async.wait_group 0;")

// ---------------- starts ----------------
__global__ void k_starts(const int* __restrict__ batch, int N, int B) {
    int b = threadIdx.x;
    if (b > B) return;
    int lo = 0, hi = N;
    while (lo < hi) {
        int mid = (lo + hi) >> 1;
        if (batch[mid] < b) lo = mid + 1; else hi = mid;
    }
    g_starts[b] = lo;
}

// ---------------- weight split (all 6 matrices, pre-paired along k) ----------------
__global__ void k_splitW(const float* __restrict__ Wq, const float* __restrict__ Wk,
                         const float* __restrict__ Wv, const float* __restrict__ Wo,
                         const float* __restrict__ W1, const float* __restrict__ W2) {
    int t = blockIdx.x * 256 + threadIdx.x;
    if (t >= WTOT) return;
    const float* W; int rel; bool n1024 = false;
    if      (t < WK_OFF) { W = Wq; rel = t; }
    else if (t < WV_OFF) { W = Wk; rel = t - WK_OFF; }
    else if (t < WO_OFF) { W = Wv; rel = t - WV_OFF; }
    else if (t < W1_OFF) { W = Wo; rel = t - WO_OFF; }
    else if (t < W2_OFF) { W = W1; rel = t - W1_OFF; n1024 = true; }
    else                 { W = W2; rel = t - W2_OFF; }
    int N = n1024 ? 1024 : 512;
    int k2 = n1024 ? (rel >> 10) : (rel >> 9);
    int n  = rel & (N - 1);
    float f0 = W[(size_t)(2 * k2) * N + n];
    float f1 = W[(size_t)(2 * k2 + 1) * N + n];
    unsigned h, l;
    splitpair(f0, f1, h, l);
    g_wh[t] = h; g_wl[t] = l;
}

// ---------------- compact input [x; CLS] -> fp32 + planes ----------------
__global__ void k_xc(const float* __restrict__ x, const float* __restrict__ cls, int N) {
    int row = blockIdx.x;
    int tid = threadIdx.x;
    const float* src = (row < N) ? (x + (size_t)row * D512)
                                 : (cls + (size_t)(row - N) * D512);
    float4 v = ((const float4*)src)[tid];
    ((float4*)(g_xc + (size_t)row * D512))[tid] = v;
    unsigned h0, l0, h1, l1;
    splitpair(v.x, v.y, h0, l0);
    splitpair(v.z, v.w, h1, l1);
    size_t p = (size_t)row * 256 + 2 * tid;
    g_xch[p] = h0; g_xch[p + 1] = h1;
    g_xcl[p] = l0; g_xcl[p + 1] = l1;
}

// ---------------- pipelined split-bf16 GEMM ----------------
// A planes [M][K/2] u32, B planes pre-paired [K/2][N] u32. 128x128 tile, K-chunk 32,
// 2-stage cp.async double buffer, ldmatrix A-frags, 256 threads (8 warps, 64x32 each).
#define STGU 9472               // u32 per stage: A 2*2560 + B 2*2176
#define A_LO 2560
#define B_HI 5120
#define B_LO 7296
#define GEMM_SMEM_BYTES (2 * STGU * 4)   // 75776

template<bool RELU, bool HASRES, bool WF32, bool WPL>
__device__ __forceinline__ void gemm_core(
    const unsigned* __restrict__ Ah, const unsigned* __restrict__ Al,
    const unsigned* __restrict__ Bh, const unsigned* __restrict__ Bl,
    const float* __restrict__ bias, const float* __restrict__ res,
    float* __restrict__ C, unsigned* __restrict__ CPh, unsigned* __restrict__ CPl,
    int M, int N, int K)
{
    extern __shared__ unsigned sm[];
    const int Ku = K >> 1;
    int tid = threadIdx.x, lane = tid & 31, warp = tid >> 5;
    int wm = warp >> 2, wn = warp & 3;
    int brow = blockIdx.y * 128, bcol = blockIdx.x * 128;
    unsigned smb = (unsigned)__cvta_generic_to_shared(sm);

    float acc[4][4][4];
#pragma unroll
    for (int mt = 0; mt < 4; mt++)
#pragma unroll
        for (int nt = 0; nt < 4; nt++)
#pragma unroll
            for (int i = 0; i < 4; i++) acc[mt][nt][i] = 0.f;

    // copy coords
    int arow = tid >> 2, aq = tid & 3;      // A: rows arow, arow+64; 16B quarter aq
    int bk2  = tid >> 5, bq = tid & 31;     // B: k2 rows bk2, bk2+8; 16B chunk bq
    int ag0 = brow + arow, ag1 = ag0 + 64;
    int as0 = (ag0 < M) ? 16 : 0, as1 = (ag1 < M) ? 16 : 0;
    const unsigned* Ar0h = Ah + (size_t)((ag0 < M) ? ag0 : 0) * Ku + aq * 4;
    const unsigned* Ar1h = Ah + (size_t)((ag1 < M) ? ag1 : 0) * Ku + aq * 4;
    const unsigned* Ar0l = Al + (size_t)((ag0 < M) ? ag0 : 0) * Ku + aq * 4;
    const unsigned* Ar1l = Al + (size_t)((ag1 < M) ? ag1 : 0) * Ku + aq * 4;
    const unsigned* B0h = Bh + (size_t)bk2 * N + bcol + bq * 4;
    const unsigned* B1h = Bh + (size_t)(bk2 + 8) * N + bcol + bq * 4;
    const unsigned* B0l = Bl + (size_t)bk2 * N + bcol + bq * 4;
    const unsigned* B1l = Bl + (size_t)(bk2 + 8) * N + bcol + bq * 4;
    unsigned dA0 = smb + 4 * (arow * 20 + aq * 4);
    unsigned dA1 = smb + 4 * ((arow + 64) * 20 + aq * 4);
    unsigned dB0 = smb + 4 * (B_HI + bk2 * 136 + bq * 4);
    unsigned dB1 = smb + 4 * (B_HI + (bk2 + 8) * 136 + bq * 4);

    int nch = K >> 5;

    auto issue = [&](int st, int ch) {
        unsigned so = st * (STGU * 4);
        int ko = ch * 16;                      // u32 k-offset into planes
        cpa16(so + dA0,            Ar0h + ko, as0);
        cpa16(so + dA1,            Ar1h + ko, as1);
        cpa16(so + dA0 + A_LO * 4, Ar0l + ko, as0);
        cpa16(so + dA1 + A_LO * 4, Ar1l + ko, as1);
        size_t bko = (size_t)ko * N;
        cpa16(so + dB0,                      B0h + bko, 16);
        cpa16(so + dB1,                      B1h + bko, 16);
        cpa16(so + dB0 + (B_LO - B_HI) * 4,  B0l + bko, 16);
        cpa16(so + dB1 + (B_LO - B_HI) * 4,  B1l + bko, 16);
        CP_COMMIT();
    };

    issue(0, 0);

    int r = lane >> 2, cl = lane & 3;
    int lrow = lane & 15, kq = lane >> 4;
    for (int ch = 0; ch < nch; ch++) {
        CP_WAIT0();
        __syncthreads();
        if (ch + 1 < nch) issue((ch + 1) & 1, ch + 1);
        int base = (ch & 1) * STGU;
#pragma unroll
        for (int s = 0; s < 2; s++) {
            unsigned ah[4][4], al[4][4];
#pragma unroll
            for (int mt = 0; mt < 4; mt++) {
                unsigned ao_ = smb + 4 * (base + (wm * 64 + mt * 16 + lrow) * 20 + s * 8 + kq * 4);
                ldm4(ah[mt], ao_);
                ldm4(al[mt], ao_ + A_LO * 4);
            }
            unsigned bhf[4][2], blf[4][2];
#pragma unroll
            for (int nt = 0; nt < 4; nt++) {
                int o = base + B_HI + (s * 8 + cl) * 136 + wn * 32 + nt * 8 + r;
                bhf[nt][0] = sm[o];           bhf[nt][1] = sm[o + 4 * 136];
                blf[nt][0] = sm[o + 2176];    blf[nt][1] = sm[o + 2176 + 4 * 136];
            }
#pragma unroll
            for (int mt = 0; mt < 4; mt++)
#pragma unroll
                for (int nt = 0; nt < 4; nt++) {
                    mma16(acc[mt][nt], ah[mt], bhf[nt]);
                    mma16(acc[mt][nt], al[mt], bhf[nt]);
                    mma16(acc[mt][nt], ah[mt], blf[nt]);
                }
        }
        __syncthreads();
    }

    // epilogue
#pragma unroll
    for (int mt = 0; mt < 4; mt++) {
        int row0 = brow + wm * 64 + mt * 16 + r;
        int row1 = row0 + 8;
#pragma unroll
        for (int nt = 0; nt < 4; nt++) {
            int col = bcol + wn * 32 + nt * 8 + cl * 2;
            float2 bb = *(const float2*)(bias + col);
            const float* c = acc[mt][nt];
#pragma unroll
            for (int half = 0; half < 2; half++) {
                int row = half ? row1 : row0;
                if (row < M) {
                    float v0 = c[2 * half] + bb.x, v1 = c[2 * half + 1] + bb.y;
                    if (HASRES) {
                        float2 rv = *(const float2*)(res + (size_t)row * N + col);
                        v0 += rv.x; v1 += rv.y;
                    }
                    if (RELU) { v0 = fmaxf(v0, 0.f); v1 = fmaxf(v1, 0.f); }
                    if (WF32)
                        *(float2*)(C + (size_t)row * N + col) = make_float2(v0, v1);
                    if (WPL) {
                        unsigned h, l;
                        splitpair(v0, v1, h, l);
                        size_t p = ((size_t)row * N + col) >> 1;
                        CPh[p] = h; CPl[p] = l;
                    }
                }
            }
        }
    }
}

// fused QKV (blockIdx.z selects weight/bias/output)
__global__ void __launch_bounds__(256) k_qkv(
    const float* __restrict__ bq, const float* __restrict__ bk,
    const float* __restrict__ bv, int M)
{
    const unsigned* Bh; const unsigned* Bl; const float* bias; float* C;
    if (blockIdx.z == 0)      { Bh = g_wh + WQ_OFF; Bl = g_wl + WQ_OFF; bias = bq; C = g_q; }
    else if (blockIdx.z == 1) { Bh = g_wh + WK_OFF; Bl = g_wl + WK_OFF; bias = bk; C = g_k; }
    else                      { Bh = g_wh + WV_OFF; Bl = g_wl + WV_OFF; bias = bv; C = g_v; }
    gemm_core<false, false, true, false>(g_xch, g_xcl, Bh, Bl, bias,
        (const float*)0, C, (unsigned*)0, (unsigned*)0, M, 512, 512);
}
__global__ void __launch_bounds__(256) k_wo(const float* __restrict__ bo, int M) {
    gemm_core<false, true, true, false>(g_ath, g_atl, g_wh + WO_OFF, g_wl + WO_OFF,
        bo, g_xc, g_ao, (unsigned*)0, (unsigned*)0, M, 512, 512);
}
__global__ void __launch_bounds__(256) k_ffn1(const float* __restrict__ b1, int M) {
    gemm_core<true, false, false, true>(g_hnh, g_hnl, g_wh + W1_OFF, g_wl + W1_OFF,
        b1, (const float*)0, (float*)0, g_th, g_tl, M, 1024, 512);
}
__global__ void __launch_bounds__(256) k_ffn2(const float* __restrict__ b2, int M) {
    gemm_core<false, true, true, false>(g_th, g_tl, g_wh + W2_OFF, g_wl + W2_OFF,
        b2, g_hn, g_f, (unsigned*)0, (unsigned*)0, M, 512, 1024);
}

// ---------------- tensor-core flash attention (R5 core; epilogue -> split planes) ----------------
#define AST 36

__global__ void __launch_bounds__(128) k_attn_mma(int N) {
    __shared__ unsigned KsHi[64*AST], KsLo[64*AST];
    __shared__ unsigned VtHi[64*AST], VtLo[64*AST];
    int b = blockIdx.z, h = blockIdx.y, qt = blockIdx.x;
    int st = g_starts[b];
    int cnt = g_starts[b + 1] - st;
    int Lb = cnt + 1;
    if (qt * 64 >= Lb) return;
    int tid = threadIdx.x, lane = tid & 31, warp = tid >> 5;
    int lr = lane >> 2, lc = lane & 3;

    {
        int r = tid >> 1, half = tid & 1;
        int qi = qt * 64 + r;
        int grow = (qi < cnt) ? st + qi : N + b;
        const float* qp = g_q + (size_t)grow * D512 + h * DH + half * 32;
        unsigned hh[16], ll[16];
#pragma unroll
        for (int j = 0; j < 8; j++) {
            float4 f = ((const float4*)qp)[j];
            splitpair(f.x, f.y, hh[2*j],   ll[2*j]);
            splitpair(f.z, f.w, hh[2*j+1], ll[2*j+1]);
        }
        int base = r * AST + half * 16;
#pragma unroll
        for (int i = 0; i < 4; i++) {
            *(uint4*)(KsHi + base + 4*i) = make_uint4(hh[4*i], hh[4*i+1], hh[4*i+2], hh[4*i+3]);
            *(uint4*)(KsLo + base + 4*i) = make_uint4(ll[4*i], ll[4*i+1], ll[4*i+2], ll[4*i+3]);
        }
    }
    __syncthreads();
    unsigned qh[4][4], qlo[4][4];
    {
        int rq = warp * 16 + lr;
#pragma unroll
        for (int ks = 0; ks < 4; ks++) {
            int c0 = ks * 8 + lc;
            qh[ks][0]  = KsHi[rq*AST + c0];      qh[ks][1]  = KsHi[(rq+8)*AST + c0];
            qh[ks][2]  = KsHi[rq*AST + c0 + 4];  qh[ks][3]  = KsHi[(rq+8)*AST + c0 + 4];
            qlo[ks][0] = KsLo[rq*AST + c0];      qlo[ks][1] = KsLo[(rq+8)*AST + c0];
            qlo[ks][2] = KsLo[rq*AST + c0 + 4];  qlo[ks][3] = KsLo[(rq+8)*AST + c0 + 4];
        }
    }
    __syncthreads();

    float m0 = -1e30f, m1 = -1e30f, l0 = 0.f, l1 = 0.f;
    float o[8][4];
#pragma unroll
    for (int nt = 0; nt < 8; nt++)
#pragma unroll
        for (int i = 0; i < 4; i++) o[nt][i] = 0.f;

    int nch = (Lb + 63) >> 6;
    for (int kt = 0; kt < nch; kt++) {
        {
            int r = tid >> 1, half = tid & 1;
            int ki = kt * 64 + r;
            int grow = (ki < cnt) ? st + ki : N + b;
            const float* kp = g_k + (size_t)grow * D512 + h * DH + half * 32;
            unsigned hh[16], ll[16];
#pragma unroll
            for (int j = 0; j < 8; j++) {
                float4 f = ((const float4*)kp)[j];
                splitpair(f.x, f.y, hh[2*j],   ll[2*j]);
                splitpair(f.z, f.w, hh[2*j+1], ll[2*j+1]);
            }
            int base = r * AST + half * 16;
#pragma unroll
            for (int i = 0; i < 4; i++) {
                *(uint4*)(KsHi + base + 4*i) = make_uint4(hh[4*i], hh[4*i+1], hh[4*i+2], hh[4*i+3]);
                *(uint4*)(KsLo + base + 4*i) = make_uint4(ll[4*i], ll[4*i+1], ll[4*i+2], ll[4*i+3]);
            }
        }
        {
            int k0i = kt * 64 + 2 * lane;
            int gr0 = (k0i     < cnt) ? st + k0i     : N + b;
            int gr1 = (k0i + 1 < cnt) ? st + k0i + 1 : N + b;
            const float* v0 = g_v + (size_t)gr0 * D512 + h * DH + warp * 16;
            const float* v1 = g_v + (size_t)gr1 * D512 + h * DH + warp * 16;
#pragma unroll
            for (int j = 0; j < 4; j++) {
                float4 f0 = ((const float4*)v0)[j];
                float4 f1 = ((const float4*)v1)[j];
                int d = warp * 16 + 4 * j;
                unsigned hx, lx;
                splitpair(f0.x, f1.x, hx, lx); VtHi[(d+0)*AST + lane] = hx; VtLo[(d+0)*AST + lane] = lx;
                splitpair(f0.y, f1.y, hx, lx); VtHi[(d+1)*AST + lane] = hx; VtLo[(d+1)*AST + lane] = lx;
                splitpair(f0.z, f1.z, hx, lx); VtHi[(d+2)*AST + lane] = hx; VtLo[(d+2)*AST + lane] = lx;
                splitpair(f0.w, f1.w, hx, lx); VtHi[(d+3)*AST + lane] = hx; VtLo[(d+3)*AST + lane] = lx;
            }
        }
        __syncthreads();

        float s[8][4];
#pragma unroll
        for (int nt = 0; nt < 8; nt++) {
            s[nt][0] = s[nt][1] = s[nt][2] = s[nt][3] = 0.f;
#pragma unroll
            for (int ks = 0; ks < 4; ks++) {
                int ko = (nt * 8 + lr) * AST + ks * 8 + lc;
                unsigned bh[2] = {KsHi[ko], KsHi[ko + 4]};
                unsigned bl[2] = {KsLo[ko], KsLo[ko + 4]};
                mma16(s[nt], qh[ks],  bh);
                mma16(s[nt], qlo[ks], bh);
                mma16(s[nt], qh[ks],  bl);
            }
        }
        int cb = kt * 64 + 2 * lc;
#pragma unroll
        for (int nt = 0; nt < 8; nt++) {
            int c0 = cb + nt * 8, c1 = c0 + 1;
            bool v0 = c0 < Lb, v1 = c1 < Lb;
            s[nt][0] = v0 ? s[nt][0] * 0.125f : -1e30f;
            s[nt][1] = v1 ? s[nt][1] * 0.125f : -1e30f;
            s[nt][2] = v0 ? s[nt][2] * 0.125f : -1e30f;
            s[nt][3] = v1 ? s[nt][3] * 0.125f : -1e30f;
        }
        float cm0 = -1e30f, cm1 = -1e30f;
#pragma unroll
        for (int nt = 0; nt < 8; nt++) {
            cm0 = fmaxf(cm0, fmaxf(s[nt][0], s[nt][1]));
            cm1 = fmaxf(cm1, fmaxf(s[nt][2], s[nt][3]));
        }
        cm0 = fmaxf(cm0, __shfl_xor_sync(0xffffffffu, cm0, 1));
        cm0 = fmaxf(cm0, __shfl_xor_sync(0xffffffffu, cm0, 2));
        cm1 = fmaxf(cm1, __shfl_xor_sync(0xffffffffu, cm1, 1));
        cm1 = fmaxf(cm1, __shfl_xor_sync(0xffffffffu, cm1, 2));
        float mn0 = fmaxf(m0, cm0), mn1 = fmaxf(m1, cm1);
        float corr0 = __expf(m0 - mn0), corr1 = __expf(m1 - mn1);
        m0 = mn0; m1 = mn1;

        float sum0 = 0.f, sum1 = 0.f;
        unsigned pah[4][4], pal[4][4];
#pragma unroll
        for (int nt = 0; nt < 8; nt++) {
            float p0 = __expf(s[nt][0] - m0), p1 = __expf(s[nt][1] - m0);
            float p2 = __expf(s[nt][2] - m1), p3 = __expf(s[nt][3] - m1);
            sum0 += p0 + p1; sum1 += p2 + p3;
            unsigned h01, l01, h23, l23;
            splitpair(p0, p1, h01, l01);
            splitpair(p2, p3, h23, l23);
            int kq = nt >> 1, sl = (nt & 1) * 2;
            pah[kq][sl] = h01; pah[kq][sl + 1] = h23;
            pal[kq][sl] = l01; pal[kq][sl + 1] = l23;
        }
        sum0 += __shfl_xor_sync(0xffffffffu, sum0, 1);
        sum0 += __shfl_xor_sync(0xffffffffu, sum0, 2);
        sum1 += __shfl_xor_sync(0xffffffffu, sum1, 1);
        sum1 += __shfl_xor_sync(0xffffffffu, sum1, 2);
        l0 = l0 * corr0 + sum0;
        l1 = l1 * corr1 + sum1;
#pragma unroll
        for (int nt = 0; nt < 8; nt++) {
            o[nt][0] *= corr0; o[nt][1] *= corr0;
            o[nt][2] *= corr1; o[nt][3] *= corr1;
        }
#pragma unroll
        for (int nt = 0; nt < 8; nt++) {
#pragma unroll
            for (int kq = 0; kq < 4; kq++) {
                int vo = (nt * 8 + lr) * AST + kq * 8 + lc;
                unsigned bh[2] = {VtHi[vo], VtHi[vo + 4]};
                unsigned bl[2] = {VtLo[vo], VtLo[vo + 4]};
                mma16(o[nt], pah[kq], bh);
                mma16(o[nt], pal[kq], bh);
                mma16(o[nt], pah[kq], bl);
            }
        }
        __syncthreads();
    }

    float inv0 = 1.f / l0, inv1 = 1.f / l1;
    int q0 = qt * 64 + warp * 16 + lr;
    int q1 = q0 + 8;
    if (q0 < Lb) {
        int gr = (q0 < cnt) ? st + q0 : N + b;
        size_t p = (size_t)gr * 256 + h * 32 + lc;
#pragma unroll
        for (int nt = 0; nt < 8; nt++) {
            unsigned hh, ll;
            splitpair(o[nt][0] * inv0, o[nt][1] * inv0, hh, ll);
            g_ath[p + nt * 4] = hh; g_atl[p + nt * 4] = ll;
        }
    }
    if (q1 < Lb) {
        int gr = (q1 < cnt) ? st + q1 : N + b;
        size_t p = (size_t)gr * 256 + h * 32 + lc;
#pragma unroll
        for (int nt = 0; nt < 8; nt++) {
            unsigned hh, ll;
            splitpair(o[nt][2] * inv1, o[nt][3] * inv1, hh, ll);
            g_ath[p + nt * 4] = hh; g_atl[p + nt * 4] = ll;
        }
    }
}

// ---------------- LayerNorm ----------------
template<bool PLANES>
__device__ __forceinline__ void row_ln(const float* __restrict__ src,
                                       const float* __restrict__ gam,
                                       const float* __restrict__ bet,
                                       float* __restrict__ dst,
                                       unsigned* __restrict__ ph,
                                       unsigned* __restrict__ pl,
                                       int row) {
    int tid = threadIdx.x;
    float4 v = ((const float4*)src)[tid];
    float s  = v.x + v.y + v.z + v.w;
    float ss = v.x*v.x + v.y*v.y + v.z*v.z + v.w*v.w;
#pragma unroll
    for (int off = 16; off; off >>= 1) {
        s  += __shfl_xor_sync(0xffffffffu, s,  off);
        ss += __shfl_xor_sync(0xffffffffu, ss, off);
    }
    __shared__ float sh[4][2];
    int w = tid >> 5;
    if ((tid & 31) == 0) { sh[w][0] = s; sh[w][1] = ss; }
    __syncthreads();
    s  = sh[0][0] + sh[1][0] + sh[2][0] + sh[3][0];
    ss = sh[0][1] + sh[1][1] + sh[2][1] + sh[3][1];
    float mean = s * (1.f / 512.f);
    float var  = ss * (1.f / 512.f) - mean * mean;
    float rr = rsqrtf(var + 1e-5f);
    float4 gg = ((const float4*)gam)[tid];
    float4 bb = ((const float4*)bet)[tid];
    float4 out;
    out.x = (v.x - mean) * rr * gg.x + bb.x;
    out.y = (v.y - mean) * rr * gg.y + bb.y;
    out.z = (v.z - mean) * rr * gg.z + bb.z;
    out.w = (v.w - mean) * rr * gg.w + bb.w;
    ((float4*)dst)[tid] = out;
    if (PLANES) {
        unsigned h0, l0, h1, l1;
        splitpair(out.x, out.y, h0, l0);
        splitpair(out.z, out.w, h1, l1);
        size_t p = (size_t)row * 256 + 2 * tid;
        ph[p] = h0; ph[p + 1] = h1;
        pl[p] = l0; pl[p + 1] = l1;
    }
}

__global__ void k_ln0(const float* __restrict__ gam, const float* __restrict__ bet) {
    int row = blockIdx.x;
    row_ln<true>(g_ao + (size_t)row * D512, gam, bet,
                 g_hn + (size_t)row * D512, g_hnh, g_hnl, row);
}
__global__ void k_ln1(const float* __restrict__ gam, const float* __restrict__ bet,
                      float* __restrict__ out) {
    int row = blockIdx.x;
    row_ln<false>(g_f + (size_t)row * D512, gam, bet,
                  out + (size_t)row * D512, (unsigned*)0, (unsigned*)0, row);
}

// ---------------- launch ----------------
extern "C" void kernel_launch(void* const* d_in, const int* in_sizes, int n_in,
                              void* d_out, int out_size) {
    const float* x     = (const float*)d_in[0];
    const int*   batch = (const int*)  d_in[1];
    const float* cls   = (const float*)d_in[2];
    const float* Wq = (const float*)d_in[3];  const float* bq = (const float*)d_in[4];
    const float* Wk = (const float*)d_in[5];  const float* bk = (const float*)d_in[6];
    const float* Wv = (const float*)d_in[7];  const float* bv = (const float*)d_in[8];
    const float* Wo = (const float*)d_in[9];  const float* bo = (const float*)d_in[10];
    const float* W1 = (const float*)d_in[11]; const float* b1 = (const float*)d_in[12];
    const float* W2 = (const float*)d_in[13]; const float* b2 = (const float*)d_in[14];
    const float* g0 = (const float*)d_in[15]; const float* be0 = (const float*)d_in[16];
    const float* ga1 = (const float*)d_in[17]; const float* be1 = (const float*)d_in[18];

    int N = in_sizes[0] / D512;      // 16384
    int B = in_sizes[2] / D512;      // 32
    int M2 = N + B;                  // 16416

    cudaFuncSetAttribute(k_qkv,  cudaFuncAttributeMaxDynamicSharedMemorySize, GEMM_SMEM_BYTES);
    cudaFuncSetAttribute(k_wo,   cudaFuncAttributeMaxDynamicSharedMemorySize, GEMM_SMEM_BYTES);
    cudaFuncSetAttribute(k_ffn1, cudaFuncAttributeMaxDynamicSharedMemorySize, GEMM_SMEM_BYTES);
    cudaFuncSetAttribute(k_ffn2, cudaFuncAttributeMaxDynamicSharedMemorySize, GEMM_SMEM_BYTES);

    k_starts<<<1, 64>>>(batch, N, B);
    k_splitW<<<WTOT / 256, 256>>>(Wq, Wk, Wv, Wo, W1, W2);
    k_xc<<<M2, 128>>>(x, cls, N);

    int my = (M2 + 127) / 128;       // 129
    k_qkv<<<dim3(4, my, 3), 256, GEMM_SMEM_BYTES>>>(bq, bk, bv, M2);

    k_attn_mma<<<dim3(13, NH, B), 128>>>(N);

    k_wo<<<dim3(4, my), 256, GEMM_SMEM_BYTES>>>(bo, M2);

    k_ln0<<<M2, 128>>>(g0, be0);

    k_ffn1<<<dim3(8, my), 256, GEMM_SMEM_BYTES>>>(b1, M2);
    k_ffn2<<<dim3(4, my), 256, GEMM_SMEM_BYTES>>>(b2, M2);

    k_ln1<<<M2, 128>>>(ga1, be1, (float*)d_out);
}

// round 9
// speedup vs baseline: 4.7872x; 1.0818x over previous
#include <cuda_runtime.h>
#include <cuda_bf16.h>
#include <math.h>

// ---------------- problem constants ----------------
#define D512 512
#define NH   8
#define DH   64
#define BMAX 32
#define NMAX 16384
#define MROWS (NMAX + BMAX)   // 16416

// ---------------- fp32 scratch ----------------
__device__ __align__(256) float g_xc[MROWS * D512];
__device__ __align__(256) float g_ao[MROWS * D512];
__device__ __align__(256) float g_hn[MROWS * D512];
__device__ __align__(256) float g_f [MROWS * D512];
__device__ int g_starts[BMAX + 1];

// ---------------- bf16 split planes (u32 = 2 bf16, low half = even index) ----------------
__device__ __align__(256) unsigned g_xch[MROWS * 256], g_xcl[MROWS * 256];
__device__ __align__(256) unsigned g_qh [MROWS * 256], g_ql [MROWS * 256];
__device__ __align__(256) unsigned g_kh [MROWS * 256], g_kl [MROWS * 256];
__device__ __align__(256) unsigned g_vh [MROWS * 256], g_vl [MROWS * 256];
__device__ __align__(256) unsigned g_ath[MROWS * 256], g_atl[MROWS * 256];
__device__ __align__(256) unsigned g_hnh[MROWS * 256], g_hnl[MROWS * 256];
__device__ __align__(256) unsigned g_th [MROWS * 512], g_tl [MROWS * 512];
// weight planes, pre-paired along k: u32 at [k2*N + n] = {W[2k2][n], W[2k2+1][n]}
#define WQ_OFF 0
#define WK_OFF 131072
#define WV_OFF 262144
#define WO_OFF 393216
#define W1_OFF 524288
#define W2_OFF 786432
#define WTOT   1048576
__device__ __align__(256) unsigned g_wh[WTOT], g_wl[WTOT];

// ---------------- helpers ----------------
__device__ __forceinline__ void splitpair(float x, float y, unsigned& h, unsigned& l) {
    __nv_bfloat16 hx = __float2bfloat16_rn(x);
    __nv_bfloat16 hy = __float2bfloat16_rn(y);
    __nv_bfloat16 lx = __float2bfloat16_rn(x - __bfloat162float(hx));
    __nv_bfloat16 ly = __float2bfloat16_rn(y - __bfloat162float(hy));
    __nv_bfloat162 hh; hh.x = hx; hh.y = hy;
    __nv_bfloat162 ll; ll.x = lx; ll.y = ly;
    h = *(unsigned*)&hh; l = *(unsigned*)&ll;
}
__device__ __forceinline__ void mma16(float* c, const unsigned* a, const unsigned* b) {
    asm volatile(
        "mma.sync.aligned.m16n8k16.row.col.f32.bf16.bf16.f32 "
        "{%0,%1,%2,%3}, {%4,%5,%6,%7}, {%8,%9}, {%0,%1,%2,%3};"
        : "+f"(c[0]), "+f"(c[1]), "+f"(c[2]), "+f"(c[3])
        : "r"(a[0]), "r"(a[1]), "r"(a[2]), "r"(a[3]), "r"(b[0]), "r"(b[1]));
}
__device__ __forceinline__ void ldm4(unsigned* d, unsigned a) {
    asm volatile("ldmatrix.sync.aligned.m8n8.x4.shared.b16 {%0,%1,%2,%3}, [%4];"
        : "=r"(d[0]), "=r"(d[1]), "=r"(d[2]), "=r"(d[3]) : "r"(a));
}
__device__ __forceinline__ void ldm4t(unsigned* d, unsigned a) {
    asm volatile("ldmatrix.sync.aligned.m8n8.x4.trans.shared.b16 {%0,%1,%2,%3}, [%4];"
        : "=r"(d[0]), "=r"(d[1]), "=r"(d[2]), "=r"(d[3]) : "r"(a));
}
__device__ __forceinline__ void cpa16(unsigned dst, const void* src, int sz) {
    asm volatile("cp.async.cg.shared.global [%0], [%1], 16, %2;"
        :: "r"(dst), "l"(src), "r"(sz));
}
#define CP_COMMIT() asm volatile("cp.async.commit_group;")
#define CP_WAIT0()  asm volatile("cp.async.wait_group 0;")

// ---------------- starts ----------------
__global__ void k_starts(const int* __restrict__ batch, int N, int B) {
    int b = threadIdx.x;
    if (b > B) return;
    int lo = 0, hi = N;
    while (lo < hi) {
        int mid = (lo + hi) >> 1;
        if (batch[mid] < b) lo = mid + 1; else hi = mid;
    }
    g_starts[b] = lo;
}

// ---------------- weight split ----------------
__global__ void k_splitW(const float* __restrict__ Wq, const float* __restrict__ Wk,
                         const float* __restrict__ Wv, const float* __restrict__ Wo,
                         const float* __restrict__ W1, const float* __restrict__ W2) {
    int t = blockIdx.x * 256 + threadIdx.x;
    if (t >= WTOT) return;
    const float* W; int rel; bool n1024 = false;
    if      (t < WK_OFF) { W = Wq; rel = t; }
    else if (t < WV_OFF) { W = Wk; rel = t - WK_OFF; }
    else if (t < WO_OFF) { W = Wv; rel = t - WV_OFF; }
    else if (t < W1_OFF) { W = Wo; rel = t - WO_OFF; }
    else if (t < W2_OFF) { W = W1; rel = t - W1_OFF; n1024 = true; }
    else                 { W = W2; rel = t - W2_OFF; }
    int N = n1024 ? 1024 : 512;
    int k2 = n1024 ? (rel >> 10) : (rel >> 9);
    int n  = rel & (N - 1);
    float f0 = W[(size_t)(2 * k2) * N + n];
    float f1 = W[(size_t)(2 * k2 + 1) * N + n];
    unsigned h, l;
    splitpair(f0, f1, h, l);
    g_wh[t] = h; g_wl[t] = l;
}

// ---------------- compact input [x; CLS] -> fp32 + planes ----------------
__global__ void k_xc(const float* __restrict__ x, const float* __restrict__ cls, int N) {
    int row = blockIdx.x;
    int tid = threadIdx.x;
    const float* src = (row < N) ? (x + (size_t)row * D512)
                                 : (cls + (size_t)(row - N) * D512);
    float4 v = ((const float4*)src)[tid];
    ((float4*)(g_xc + (size_t)row * D512))[tid] = v;
    unsigned h0, l0, h1, l1;
    splitpair(v.x, v.y, h0, l0);
    splitpair(v.z, v.w, h1, l1);
    size_t p = (size_t)row * 256 + 2 * tid;
    g_xch[p] = h0; g_xch[p + 1] = h1;
    g_xcl[p] = l0; g_xcl[p + 1] = l1;
}

// ---------------- pipelined split-bf16 GEMM ----------------
#define STGU 9472
#define A_LO 2560
#define B_HI 5120
#define B_LO 7296
#define GEMM_SMEM_BYTES (2 * STGU * 4)   // 75776

template<bool RELU, bool HASRES, bool WF32, bool WPL>
__device__ __forceinline__ void gemm_core(
    const unsigned* __restrict__ Ah, const unsigned* __restrict__ Al,
    const unsigned* __restrict__ Bh, const unsigned* __restrict__ Bl,
    const float* __restrict__ bias, const float* __restrict__ res,
    float* __restrict__ C, unsigned* __restrict__ CPh, unsigned* __restrict__ CPl,
    int M, int N, int K)
{
    extern __shared__ unsigned sm[];
    const int Ku = K >> 1;
    int tid = threadIdx.x, lane = tid & 31, warp = tid >> 5;
    int wm = warp >> 2, wn = warp & 3;
    int brow = blockIdx.y * 128, bcol = blockIdx.x * 128;
    unsigned smb = (unsigned)__cvta_generic_to_shared(sm);

    float acc[4][4][4];
#pragma unroll
    for (int mt = 0; mt < 4; mt++)
#pragma unroll
        for (int nt = 0; nt < 4; nt++)
#pragma unroll
            for (int i = 0; i < 4; i++) acc[mt][nt][i] = 0.f;

    int arow = tid >> 2, aq = tid & 3;
    int bk2  = tid >> 5, bq = tid & 31;
    int ag0 = brow + arow, ag1 = ag0 + 64;
    int as0 = (ag0 < M) ? 16 : 0, as1 = (ag1 < M) ? 16 : 0;
    const unsigned* Ar0h = Ah + (size_t)((ag0 < M) ? ag0 : 0) * Ku + aq * 4;
    const unsigned* Ar1h = Ah + (size_t)((ag1 < M) ? ag1 : 0) * Ku + aq * 4;
    const unsigned* Ar0l = Al + (size_t)((ag0 < M) ? ag0 : 0) * Ku + aq * 4;
    const unsigned* Ar1l = Al + (size_t)((ag1 < M) ? ag1 : 0) * Ku + aq * 4;
    const unsigned* B0h = Bh + (size_t)bk2 * N + bcol + bq * 4;
    const unsigned* B1h = Bh + (size_t)(bk2 + 8) * N + bcol + bq * 4;
    const unsigned* B0l = Bl + (size_t)bk2 * N + bcol + bq * 4;
    const unsigned* B1l = Bl + (size_t)(bk2 + 8) * N + bcol + bq * 4;
    unsigned dA0 = smb + 4 * (arow * 20 + aq * 4);
    unsigned dA1 = smb + 4 * ((arow + 64) * 20 + aq * 4);
    unsigned dB0 = smb + 4 * (B_HI + bk2 * 136 + bq * 4);
    unsigned dB1 = smb + 4 * (B_HI + (bk2 + 8) * 136 + bq * 4);

    int nch = K >> 5;

    auto issue = [&](int st, int ch) {
        unsigned so = st * (STGU * 4);
        int ko = ch * 16;
        cpa16(so + dA0,            Ar0h + ko, as0);
        cpa16(so + dA1,            Ar1h + ko, as1);
        cpa16(so + dA0 + A_LO * 4, Ar0l + ko, as0);
        cpa16(so + dA1 + A_LO * 4, Ar1l + ko, as1);
        size_t bko = (size_t)ko * N;
        cpa16(so + dB0,                      B0h + bko, 16);
        cpa16(so + dB1,                      B1h + bko, 16);
        cpa16(so + dB0 + (B_LO - B_HI) * 4,  B0l + bko, 16);
        cpa16(so + dB1 + (B_LO - B_HI) * 4,  B1l + bko, 16);
        CP_COMMIT();
    };

    issue(0, 0);

    int r = lane >> 2, cl = lane & 3;
    int lrow = lane & 15, kq = lane >> 4;
    for (int ch = 0; ch < nch; ch++) {
        CP_WAIT0();
        __syncthreads();
        if (ch + 1 < nch) issue((ch + 1) & 1, ch + 1);
        int base = (ch & 1) * STGU;
#pragma unroll
        for (int s = 0; s < 2; s++) {
            unsigned ah[4][4], al[4][4];
#pragma unroll
            for (int mt = 0; mt < 4; mt++) {
                unsigned ao_ = smb + 4 * (base + (wm * 64 + mt * 16 + lrow) * 20 + s * 8 + kq * 4);
                ldm4(ah[mt], ao_);
                ldm4(al[mt], ao_ + A_LO * 4);
            }
            unsigned bhf[4][2], blf[4][2];
#pragma unroll
            for (int nt = 0; nt < 4; nt++) {
                int o = base + B_HI + (s * 8 + cl) * 136 + wn * 32 + nt * 8 + r;
                bhf[nt][0] = sm[o];           bhf[nt][1] = sm[o + 4 * 136];
                blf[nt][0] = sm[o + 2176];    blf[nt][1] = sm[o + 2176 + 4 * 136];
            }
#pragma unroll
            for (int mt = 0; mt < 4; mt++)
#pragma unroll
                for (int nt = 0; nt < 4; nt++) {
                    mma16(acc[mt][nt], ah[mt], bhf[nt]);
                    mma16(acc[mt][nt], al[mt], bhf[nt]);
                    mma16(acc[mt][nt], ah[mt], blf[nt]);
                }
        }
        __syncthreads();
    }

#pragma unroll
    for (int mt = 0; mt < 4; mt++) {
        int row0 = brow + wm * 64 + mt * 16 + r;
        int row1 = row0 + 8;
#pragma unroll
        for (int nt = 0; nt < 4; nt++) {
            int col = bcol + wn * 32 + nt * 8 + cl * 2;
            float2 bb = *(const float2*)(bias + col);
            const float* c = acc[mt][nt];
#pragma unroll
            for (int half = 0; half < 2; half++) {
                int row = half ? row1 : row0;
                if (row < M) {
                    float v0 = c[2 * half] + bb.x, v1 = c[2 * half + 1] + bb.y;
                    if (HASRES) {
                        float2 rv = *(const float2*)(res + (size_t)row * N + col);
                        v0 += rv.x; v1 += rv.y;
                    }
                    if (RELU) { v0 = fmaxf(v0, 0.f); v1 = fmaxf(v1, 0.f); }
                    if (WF32)
                        *(float2*)(C + (size_t)row * N + col) = make_float2(v0, v1);
                    if (WPL) {
                        unsigned h, l;
                        splitpair(v0, v1, h, l);
                        size_t p = ((size_t)row * N + col) >> 1;
                        CPh[p] = h; CPl[p] = l;
                    }
                }
            }
        }
    }
}

// fused QKV -> split planes only
__global__ void __launch_bounds__(256, 2) k_qkv(
    const float* __restrict__ bq, const float* __restrict__ bk,
    const float* __restrict__ bv, int M)
{
    const unsigned* Bh; const unsigned* Bl; const float* bias;
    unsigned* Ph; unsigned* Pl;
    if (blockIdx.z == 0)      { Bh = g_wh + WQ_OFF; Bl = g_wl + WQ_OFF; bias = bq; Ph = g_qh; Pl = g_ql; }
    else if (blockIdx.z == 1) { Bh = g_wh + WK_OFF; Bl = g_wl + WK_OFF; bias = bk; Ph = g_kh; Pl = g_kl; }
    else                      { Bh = g_wh + WV_OFF; Bl = g_wl + WV_OFF; bias = bv; Ph = g_vh; Pl = g_vl; }
    gemm_core<false, false, false, true>(g_xch, g_xcl, Bh, Bl, bias,
        (const float*)0, (float*)0, Ph, Pl, M, 512, 512);
}
__global__ void __launch_bounds__(256, 2) k_wo(const float* __restrict__ bo, int M) {
    gemm_core<false, true, true, false>(g_ath, g_atl, g_wh + WO_OFF, g_wl + WO_OFF,
        bo, g_xc, g_ao, (unsigned*)0, (unsigned*)0, M, 512, 512);
}
__global__ void __launch_bounds__(256, 2) k_ffn1(const float* __restrict__ b1, int M) {
    gemm_core<true, false, false, true>(g_hnh, g_hnl, g_wh + W1_OFF, g_wl + W1_OFF,
        b1, (const float*)0, (float*)0, g_th, g_tl, M, 1024, 512);
}
__global__ void __launch_bounds__(256, 2) k_ffn2(const float* __restrict__ b2, int M) {
    gemm_core<false, true, true, false>(g_th, g_tl, g_wh + W2_OFF, g_wl + W2_OFF,
        b2, g_hn, g_f, (unsigned*)0, (unsigned*)0, M, 512, 1024);
}

// ---------------- tensor-core flash attention (planes + cp.async + ldmatrix.trans) ----------------
// smem: [0..2304) KsHi  [2304..4608) KsLo  [4608..6912) VsHi  [6912..9216) VsLo
// K/V smem layout: [row 0..63][32 u32 dim-pairs], stride 36 u32 (conflict-free).
#define AST 36
#define SM_KL 2304
#define SM_VH 4608
#define SM_VL 6912

__global__ void __launch_bounds__(128) k_attn_mma(int N) {
    __shared__ unsigned sm[9216];
    int b = blockIdx.z, h = blockIdx.y, qt = blockIdx.x;
    int st = g_starts[b];
    int cnt = g_starts[b + 1] - st;
    int Lb = cnt + 1;
    if (qt * 64 >= Lb) return;
    int tid = threadIdx.x, lane = tid & 31, warp = tid >> 5;
    int lr = lane >> 2, lc = lane & 3;
    unsigned smb = (unsigned)__cvta_generic_to_shared(sm);

    // per-thread staging coords (row = tid>>1, half-row 16 u32)
    int srow = tid >> 1, shalf = (tid & 1) * 16;
    unsigned dK = smb + 4 * (srow * AST + shalf);

    // ---- stage Q planes into K region, extract a-frags ----
    {
        int qi = qt * 64 + srow;
        int grow = (qi < cnt) ? st + qi : N + b;
        size_t so = (size_t)grow * 256 + h * 32 + shalf;
#pragma unroll
        for (int i = 0; i < 4; i++) {
            cpa16(dK + 16 * i,              g_qh + so + 4 * i, 16);
            cpa16(dK + 16 * i + SM_KL * 4,  g_ql + so + 4 * i, 16);
        }
        CP_COMMIT(); CP_WAIT0();
    }
    __syncthreads();
    unsigned qh[4][4], qlo[4][4];
    {
        int rq = warp * 16 + lr;
#pragma unroll
        for (int ks = 0; ks < 4; ks++) {
            int c0 = ks * 8 + lc;
            qh[ks][0]  = sm[rq*AST + c0];              qh[ks][1]  = sm[(rq+8)*AST + c0];
            qh[ks][2]  = sm[rq*AST + c0 + 4];          qh[ks][3]  = sm[(rq+8)*AST + c0 + 4];
            qlo[ks][0] = sm[SM_KL + rq*AST + c0];      qlo[ks][1] = sm[SM_KL + (rq+8)*AST + c0];
            qlo[ks][2] = sm[SM_KL + rq*AST + c0 + 4];  qlo[ks][3] = sm[SM_KL + (rq+8)*AST + c0 + 4];
        }
    }
    __syncthreads();

    float m0 = -1e30f, m1 = -1e30f, l0 = 0.f, l1 = 0.f;
    float o[8][4];
#pragma unroll
    for (int nt = 0; nt < 8; nt++)
#pragma unroll
        for (int i = 0; i < 4; i++) o[nt][i] = 0.f;

    // V^T ldmatrix lane addressing
    int vkey = ((lane >> 3) & 1) * 8 + (lane & 7);
    int vdof = (lane >> 4) * 4;

    int nch = (Lb + 63) >> 6;
    for (int kt = 0; kt < nch; kt++) {
        // stage K + V planes via cp.async
        {
            int ki = kt * 64 + srow;
            int grow = (ki < cnt) ? st + ki : N + b;
            size_t so = (size_t)grow * 256 + h * 32 + shalf;
#pragma unroll
            for (int i = 0; i < 4; i++) {
                cpa16(dK + 16 * i,             g_kh + so + 4 * i, 16);
                cpa16(dK + 16 * i + SM_KL * 4, g_kl + so + 4 * i, 16);
                cpa16(dK + 16 * i + SM_VH * 4, g_vh + so + 4 * i, 16);
                cpa16(dK + 16 * i + SM_VL * 4, g_vl + so + 4 * i, 16);
            }
            CP_COMMIT(); CP_WAIT0();
        }
        __syncthreads();

        // S = Q K^T (3-term split)
        float s[8][4];
#pragma unroll
        for (int nt = 0; nt < 8; nt++) {
            s[nt][0] = s[nt][1] = s[nt][2] = s[nt][3] = 0.f;
#pragma unroll
            for (int ks = 0; ks < 4; ks++) {
                int ko = (nt * 8 + lr) * AST + ks * 8 + lc;
                unsigned bh[2] = {sm[ko], sm[ko + 4]};
                unsigned bl[2] = {sm[SM_KL + ko], sm[SM_KL + ko + 4]};
                mma16(s[nt], qh[ks],  bh);
                mma16(s[nt], qlo[ks], bh);
                mma16(s[nt], qh[ks],  bl);
            }
        }
        int cb = kt * 64 + 2 * lc;
#pragma unroll
        for (int nt = 0; nt < 8; nt++) {
            int c0 = cb + nt * 8, c1 = c0 + 1;
            bool v0 = c0 < Lb, v1 = c1 < Lb;
            s[nt][0] = v0 ? s[nt][0] * 0.125f : -1e30f;
            s[nt][1] = v1 ? s[nt][1] * 0.125f : -1e30f;
            s[nt][2] = v0 ? s[nt][2] * 0.125f : -1e30f;
            s[nt][3] = v1 ? s[nt][3] * 0.125f : -1e30f;
        }
        float cm0 = -1e30f, cm1 = -1e30f;
#pragma unroll
        for (int nt = 0; nt < 8; nt++) {
            cm0 = fmaxf(cm0, fmaxf(s[nt][0], s[nt][1]));
            cm1 = fmaxf(cm1, fmaxf(s[nt][2], s[nt][3]));
        }
        cm0 = fmaxf(cm0, __shfl_xor_sync(0xffffffffu, cm0, 1));
        cm0 = fmaxf(cm0, __shfl_xor_sync(0xffffffffu, cm0, 2));
        cm1 = fmaxf(cm1, __shfl_xor_sync(0xffffffffu, cm1, 1));
        cm1 = fmaxf(cm1, __shfl_xor_sync(0xffffffffu, cm1, 2));
        float mn0 = fmaxf(m0, cm0), mn1 = fmaxf(m1, cm1);
        float corr0 = __expf(m0 - mn0), corr1 = __expf(m1 - mn1);
        m0 = mn0; m1 = mn1;

        float sum0 = 0.f, sum1 = 0.f;
        unsigned pah[4][4], pal[4][4];
#pragma unroll
        for (int nt = 0; nt < 8; nt++) {
            float p0 = __expf(s[nt][0] - m0), p1 = __expf(s[nt][1] - m0);
            float p2 = __expf(s[nt][2] - m1), p3 = __expf(s[nt][3] - m1);
            sum0 += p0 + p1; sum1 += p2 + p3;
            unsigned h01, l01, h23, l23;
            splitpair(p0, p1, h01, l01);
            splitpair(p2, p3, h23, l23);
            int kq = nt >> 1, sl = (nt & 1) * 2;
            pah[kq][sl] = h01; pah[kq][sl + 1] = h23;
            pal[kq][sl] = l01; pal[kq][sl + 1] = l23;
        }
        sum0 += __shfl_xor_sync(0xffffffffu, sum0, 1);
        sum0 += __shfl_xor_sync(0xffffffffu, sum0, 2);
        sum1 += __shfl_xor_sync(0xffffffffu, sum1, 1);
        sum1 += __shfl_xor_sync(0xffffffffu, sum1, 2);
        l0 = l0 * corr0 + sum0;
        l1 = l1 * corr1 + sum1;
#pragma unroll
        for (int nt = 0; nt < 8; nt++) {
            o[nt][0] *= corr0; o[nt][1] *= corr0;
            o[nt][2] *= corr1; o[nt][3] *= corr1;
        }
        // O += P V via ldmatrix.x4.trans on [key][dim-pair] planes
#pragma unroll
        for (int kq = 0; kq < 4; kq++) {
#pragma unroll
            for (int ntp = 0; ntp < 4; ntp++) {
                unsigned va = smb + 4 * (SM_VH + (kq * 16 + vkey) * AST + ntp * 8 + vdof);
                unsigned dh_[4], dl_[4];
                ldm4t(dh_, va);
                ldm4t(dl_, va + (SM_VL - SM_VH) * 4);
                unsigned bh01[2] = {dh_[0], dh_[1]}, bh23[2] = {dh_[2], dh_[3]};
                unsigned bl01[2] = {dl_[0], dl_[1]}, bl23[2] = {dl_[2], dl_[3]};
                mma16(o[2*ntp],     pah[kq], bh01);
                mma16(o[2*ntp],     pal[kq], bh01);
                mma16(o[2*ntp],     pah[kq], bl01);
                mma16(o[2*ntp + 1], pah[kq], bh23);
                mma16(o[2*ntp + 1], pal[kq], bh23);
                mma16(o[2*ntp + 1], pah[kq], bl23);
            }
        }
        __syncthreads();
    }

    float inv0 = 1.f / l0, inv1 = 1.f / l1;
    int q0 = qt * 64 + warp * 16 + lr;
    int q1 = q0 + 8;
    if (q0 < Lb) {
        int gr = (q0 < cnt) ? st + q0 : N + b;
        size_t p = (size_t)gr * 256 + h * 32 + lc;
#pragma unroll
        for (int nt = 0; nt < 8; nt++) {
            unsigned hh, ll;
            splitpair(o[nt][0] * inv0, o[nt][1] * inv0, hh, ll);
            g_ath[p + nt * 4] = hh; g_atl[p + nt * 4] = ll;
        }
    }
    if (q1 < Lb) {
        int gr = (q1 < cnt) ? st + q1 : N + b;
        size_t p = (size_t)gr * 256 + h * 32 + lc;
#pragma unroll
        for (int nt = 0; nt < 8; nt++) {
            unsigned hh, ll;
            splitpair(o[nt][2] * inv1, o[nt][3] * inv1, hh, ll);
            g_ath[p + nt * 4] = hh; g_atl[p + nt * 4] = ll;
        }
    }
}

// ---------------- LayerNorm ----------------
template<bool PLANES>
__device__ __forceinline__ void row_ln(const float* __restrict__ src,
                                       const float* __restrict__ gam,
                                       const float* __restrict__ bet,
                                       float* __restrict__ dst,
                                       unsigned* __restrict__ ph,
                                       unsigned* __restrict__ pl,
                                       int row) {
    int tid = threadIdx.x;
    float4 v = ((const float4*)src)[tid];
    float s  = v.x + v.y + v.z + v.w;
    float ss = v.x*v.x + v.y*v.y + v.z*v.z + v.w*v.w;
#pragma unroll
    for (int off = 16; off; off >>= 1) {
        s  += __shfl_xor_sync(0xffffffffu, s,  off);
        ss += __shfl_xor_sync(0xffffffffu, ss, off);
    }
    __shared__ float sh[4][2];
    int w = tid >> 5;
    if ((tid & 31) == 0) { sh[w][0] = s; sh[w][1] = ss; }
    __syncthreads();
    s  = sh[0][0] + sh[1][0] + sh[2][0] + sh[3][0];
    ss = sh[0][1] + sh[1][1] + sh[2][1] + sh[3][1];
    float mean = s * (1.f / 512.f);
    float var  = ss * (1.f / 512.f) - mean * mean;
    float rr = rsqrtf(var + 1e-5f);
    float4 gg = ((const float4*)gam)[tid];
    float4 bb = ((const float4*)bet)[tid];
    float4 out;
    out.x = (v.x - mean) * rr * gg.x + bb.x;
    out.y = (v.y - mean) * rr * gg.y + bb.y;
    out.z = (v.z - mean) * rr * gg.z + bb.z;
    out.w = (v.w - mean) * rr * gg.w + bb.w;
    ((float4*)dst)[tid] = out;
    if (PLANES) {
        unsigned h0, l0, h1, l1;
        splitpair(out.x, out.y, h0, l0);
        splitpair(out.z, out.w, h1, l1);
        size_t p = (size_t)row * 256 + 2 * tid;
        ph[p] = h0; ph[p + 1] = h1;
        pl[p] = l0; pl[p + 1] = l1;
    }
}

__global__ void k_ln0(const float* __restrict__ gam, const float* __restrict__ bet) {
    int row = blockIdx.x;
    row_ln<true>(g_ao + (size_t)row * D512, gam, bet,
                 g_hn + (size_t)row * D512, g_hnh, g_hnl, row);
}
__global__ void k_ln1(const float* __restrict__ gam, const float* __restrict__ bet,
                      float* __restrict__ out) {
    int row = blockIdx.x;
    row_ln<false>(g_f + (size_t)row * D512, gam, bet,
                  out + (size_t)row * D512, (unsigned*)0, (unsigned*)0, row);
}

// ---------------- launch ----------------
extern "C" void kernel_launch(void* const* d_in, const int* in_sizes, int n_in,
                              void* d_out, int out_size) {
    const float* x     = (const float*)d_in[0];
    const int*   batch = (const int*)  d_in[1];
    const float* cls   = (const float*)d_in[2];
    const float* Wq = (const float*)d_in[3];  const float* bq = (const float*)d_in[4];
    const float* Wk = (const float*)d_in[5];  const float* bk = (const float*)d_in[6];
    const float* Wv = (const float*)d_in[7];  const float* bv = (const float*)d_in[8];
    const float* Wo = (const float*)d_in[9];  const float* bo = (const float*)d_in[10];
    const float* W1 = (const float*)d_in[11]; const float* b1 = (const float*)d_in[12];
    const float* W2 = (const float*)d_in[13]; const float* b2 = (const float*)d_in[14];
    const float* g0 = (const float*)d_in[15]; const float* be0 = (const float*)d_in[16];
    const float* ga1 = (const float*)d_in[17]; const float* be1 = (const float*)d_in[18];

    int N = in_sizes[0] / D512;      // 16384
    int B = in_sizes[2] / D512;      // 32
    int M2 = N + B;                  // 16416

    cudaFuncSetAttribute(k_qkv,  cudaFuncAttributeMaxDynamicSharedMemorySize, GEMM_SMEM_BYTES);
    cudaFuncSetAttribute(k_wo,   cudaFuncAttributeMaxDynamicSharedMemorySize, GEMM_SMEM_BYTES);
    cudaFuncSetAttribute(k_ffn1, cudaFuncAttributeMaxDynamicSharedMemorySize, GEMM_SMEM_BYTES);
    cudaFuncSetAttribute(k_ffn2, cudaFuncAttributeMaxDynamicSharedMemorySize, GEMM_SMEM_BYTES);

    k_starts<<<1, 64>>>(batch, N, B);
    k_splitW<<<WTOT / 256, 256>>>(Wq, Wk, Wv, Wo, W1, W2);
    k_xc<<<M2, 128>>>(x, cls, N);

    int my = (M2 + 127) / 128;       // 129
    k_qkv<<<dim3(4, my, 3), 256, GEMM_SMEM_BYTES>>>(bq, bk, bv, M2);

    k_attn_mma<<<dim3(13, NH, B), 128>>>(N);

    k_wo<<<dim3(4, my), 256, GEMM_SMEM_BYTES>>>(bo, M2);

    k_ln0<<<M2, 128>>>(g0, be0);

    k_ffn1<<<dim3(8, my), 256, GEMM_SMEM_BYTES>>>(b1, M2);
    k_ffn2<<<dim3(4, my), 256, GEMM_SMEM_BYTES>>>(b2, M2);

    k_ln1<<<M2, 128>>>(ga1, be1, (float*)d_out);
}